// round 1
// baseline (speedup 1.0000x reference)
#include <cuda_runtime.h>
#include <math.h>

// Problem constants
#define B_WIN 4096
#define N_TOK 49
#define DIM   384
#define HEADS 12
#define HD    32
#define M_TOT (B_WIN * N_TOK)     // 200704
#define QKV_N (3 * DIM)           // 1152
#define SCALE 0.17677669529663687f  // 1/sqrt(32)

// Scratch (static device globals — allocation-guard safe)
__device__ float g_qkv[(size_t)M_TOT * QKV_N];  // [M_TOT, 1152]  q|k|v
__device__ float g_ctx[(size_t)M_TOT * DIM];    // [M_TOT, 384]   attention output

// ---------------------------------------------------------------------------
// GEMM: C[M,N] = A[M,K] @ W[N,K]^T + bias[N]
// Both A and W are K-major. Requires M%128==0, N%128==0, K%16==0 (true here).
// 128x128x16 block tile, 256 threads, 8x8 per thread, float4 everywhere.
// ---------------------------------------------------------------------------
__global__ void __launch_bounds__(256, 2) gemm_nt_bias(
    const float* __restrict__ A, const float* __restrict__ W,
    const float* __restrict__ bias, float* __restrict__ C,
    int M, int N, int K)
{
    const int BM = 128, BN = 128, BK = 16;
    __shared__ float As[16][BM + 4];
    __shared__ float Ws[16][BN + 4];

    const int tid = threadIdx.x;
    const int bm = blockIdx.y * BM;
    const int bn = blockIdx.x * BN;

    // loader: each thread loads 2 float4 per tile for A and for W
    const int lr = tid >> 2;           // 0..63
    const int lc = (tid & 3) * 4;      // 0,4,8,12

    // compute thread layout: 16 x 16
    const int tx = tid & 15;           // output col group
    const int ty = tid >> 4;           // output row group

    float acc[8][8];
    #pragma unroll
    for (int i = 0; i < 8; ++i)
        #pragma unroll
        for (int j = 0; j < 8; ++j) acc[i][j] = 0.0f;

    const float* Aptr = A + (size_t)bm * K;
    const float* Wptr = W + (size_t)bn * K;

    for (int k0 = 0; k0 < K; k0 += BK) {
        #pragma unroll
        for (int r = 0; r < BM; r += 64) {
            float4 v = *(const float4*)(Aptr + (size_t)(lr + r) * K + k0 + lc);
            As[lc + 0][lr + r] = v.x;
            As[lc + 1][lr + r] = v.y;
            As[lc + 2][lr + r] = v.z;
            As[lc + 3][lr + r] = v.w;
        }
        #pragma unroll
        for (int r = 0; r < BN; r += 64) {
            float4 v = *(const float4*)(Wptr + (size_t)(lr + r) * K + k0 + lc);
            Ws[lc + 0][lr + r] = v.x;
            Ws[lc + 1][lr + r] = v.y;
            Ws[lc + 2][lr + r] = v.z;
            Ws[lc + 3][lr + r] = v.w;
        }
        __syncthreads();

        #pragma unroll
        for (int k = 0; k < BK; ++k) {
            float a[8], b[8];
            float4 a0 = *(const float4*)&As[k][ty * 8];
            float4 a1 = *(const float4*)&As[k][ty * 8 + 4];
            float4 b0 = *(const float4*)&Ws[k][tx * 8];
            float4 b1 = *(const float4*)&Ws[k][tx * 8 + 4];
            a[0]=a0.x; a[1]=a0.y; a[2]=a0.z; a[3]=a0.w;
            a[4]=a1.x; a[5]=a1.y; a[6]=a1.z; a[7]=a1.w;
            b[0]=b0.x; b[1]=b0.y; b[2]=b0.z; b[3]=b0.w;
            b[4]=b1.x; b[5]=b1.y; b[6]=b1.z; b[7]=b1.w;
            #pragma unroll
            for (int i = 0; i < 8; ++i)
                #pragma unroll
                for (int j = 0; j < 8; ++j)
                    acc[i][j] = fmaf(a[i], b[j], acc[i][j]);
        }
        __syncthreads();
    }

    // epilogue: add bias, write out
    float bv[8];
    #pragma unroll
    for (int j = 0; j < 8; ++j) bv[j] = bias[bn + tx * 8 + j];

    #pragma unroll
    for (int i = 0; i < 8; ++i) {
        size_t row = (size_t)(bm + ty * 8 + i);
        float4 o0, o1;
        o0.x = acc[i][0] + bv[0]; o0.y = acc[i][1] + bv[1];
        o0.z = acc[i][2] + bv[2]; o0.w = acc[i][3] + bv[3];
        o1.x = acc[i][4] + bv[4]; o1.y = acc[i][5] + bv[5];
        o1.z = acc[i][6] + bv[6]; o1.w = acc[i][7] + bv[7];
        *(float4*)(C + row * N + bn + tx * 8)     = o0;
        *(float4*)(C + row * N + bn + tx * 8 + 4) = o1;
    }
}

// ---------------------------------------------------------------------------
// Attention: one CTA per (window b, head h). 128 threads.
// q,k,v [49,32] in smem; S[49,49] + rpb bias, softmax, P@V -> ctx.
// ---------------------------------------------------------------------------
__global__ void __launch_bounds__(128) attn_kernel(
    const float* __restrict__ qkv,   // [M_TOT, 1152]
    const float* __restrict__ rpb,   // [169, 12]
    const int*   __restrict__ ridx,  // [49, 49]
    float* __restrict__ ctx)         // [M_TOT, 384]
{
    const int b = blockIdx.x;
    const int h = blockIdx.y;
    const int tid = threadIdx.x;

    __shared__ float qs[N_TOK][HD + 1];
    __shared__ float ks[N_TOK][HD + 1];
    __shared__ float vs[N_TOK][HD + 1];
    __shared__ float s[N_TOK][51];

    // load q (scaled), k, v
    for (int idx = tid; idx < N_TOK * (HD / 4); idx += 128) {
        int n  = idx >> 3;           // /8
        int d4 = (idx & 7) * 4;
        size_t base = ((size_t)(b * N_TOK + n)) * QKV_N + h * HD + d4;
        float4 q4 = *(const float4*)(qkv + base);
        float4 k4 = *(const float4*)(qkv + base + DIM);
        float4 v4 = *(const float4*)(qkv + base + 2 * DIM);
        qs[n][d4 + 0] = q4.x * SCALE; qs[n][d4 + 1] = q4.y * SCALE;
        qs[n][d4 + 2] = q4.z * SCALE; qs[n][d4 + 3] = q4.w * SCALE;
        ks[n][d4 + 0] = k4.x; ks[n][d4 + 1] = k4.y;
        ks[n][d4 + 2] = k4.z; ks[n][d4 + 3] = k4.w;
        vs[n][d4 + 0] = v4.x; vs[n][d4 + 1] = v4.y;
        vs[n][d4 + 2] = v4.z; vs[n][d4 + 3] = v4.w;
    }
    __syncthreads();

    // logits + relative position bias
    for (int idx = tid; idx < N_TOK * N_TOK; idx += 128) {
        int i = idx / N_TOK, j = idx - i * N_TOK;
        float acc = rpb[ridx[idx] * HEADS + h];
        #pragma unroll
        for (int kk = 0; kk < HD; ++kk)
            acc = fmaf(qs[i][kk], ks[j][kk], acc);
        s[i][j] = acc;
    }
    __syncthreads();

    // softmax: one thread per row
    if (tid < N_TOK) {
        float m = -1e30f;
        #pragma unroll 7
        for (int j = 0; j < N_TOK; ++j) m = fmaxf(m, s[tid][j]);
        float sum = 0.0f;
        #pragma unroll 7
        for (int j = 0; j < N_TOK; ++j) {
            float e = __expf(s[tid][j] - m);
            s[tid][j] = e;
            sum += e;
        }
        float inv = 1.0f / sum;
        #pragma unroll 7
        for (int j = 0; j < N_TOK; ++j) s[tid][j] *= inv;
    }
    __syncthreads();

    // out = P @ V
    for (int idx = tid; idx < N_TOK * HD; idx += 128) {
        int i = idx >> 5;          // /32
        int d = idx & 31;
        float acc = 0.0f;
        #pragma unroll
        for (int j = 0; j < N_TOK; ++j)
            acc = fmaf(s[i][j], vs[j][d], acc);
        ctx[((size_t)(b * N_TOK + i)) * DIM + h * HD + d] = acc;
    }
}

// ---------------------------------------------------------------------------
extern "C" void kernel_launch(void* const* d_in, const int* in_sizes, int n_in,
                              void* d_out, int out_size)
{
    const float* x      = (const float*)d_in[0];
    const float* qkv_w  = (const float*)d_in[1];
    const float* qkv_b  = (const float*)d_in[2];
    const float* proj_w = (const float*)d_in[3];
    const float* proj_b = (const float*)d_in[4];
    const float* rpb    = (const float*)d_in[5];
    const int*   ridx   = (const int*)d_in[6];
    float* out = (float*)d_out;

    float* qkv_s = nullptr;
    float* ctx_s = nullptr;
    cudaGetSymbolAddress((void**)&qkv_s, g_qkv);
    cudaGetSymbolAddress((void**)&ctx_s, g_ctx);

    // 1) QKV GEMM: [200704,384] @ [1152,384]^T -> [200704,1152]
    {
        dim3 grid(QKV_N / 128, M_TOT / 128);   // (9, 1568)
        gemm_nt_bias<<<grid, 256>>>(x, qkv_w, qkv_b, qkv_s, M_TOT, QKV_N, DIM);
    }

    // 2) Attention per (window, head)
    {
        dim3 grid(B_WIN, HEADS);
        attn_kernel<<<grid, 128>>>(qkv_s, rpb, ridx, ctx_s);
    }

    // 3) Projection GEMM: [200704,384] @ [384,384]^T -> [200704,384]
    {
        dim3 grid(DIM / 128, M_TOT / 128);     // (3, 1568)
        gemm_nt_bias<<<grid, 256>>>(ctx_s, proj_w, proj_b, out, M_TOT, DIM, DIM);
    }
}

// round 3
// speedup vs baseline: 1.4991x; 1.4991x over previous
#include <cuda_runtime.h>
#include <cuda_bf16.h>
#include <math.h>
#include <stdint.h>

// Problem constants
#define B_WIN 4096
#define N_TOK 49
#define DIM   384
#define HEADS 12
#define HD    32
#define M_TOT (B_WIN * N_TOK)     // 200704
#define QKV_N (3 * DIM)           // 1152
#define KTOT  384
#define SCALE 0.17677669529663687f

// ---------------------------------------------------------------------------
// Scratch (static device globals — allocation-guard safe)
// ---------------------------------------------------------------------------
__device__ __nv_bfloat16 g_xhi[(size_t)M_TOT * DIM];
__device__ __nv_bfloat16 g_xlo[(size_t)M_TOT * DIM];
__device__ float         g_qkv[(size_t)M_TOT * QKV_N];
__device__ __nv_bfloat16 g_chi[(size_t)M_TOT * DIM];
__device__ __nv_bfloat16 g_clo[(size_t)M_TOT * DIM];
__device__ __nv_bfloat16 g_wqhi[(size_t)QKV_N * DIM];
__device__ __nv_bfloat16 g_wqlo[(size_t)QKV_N * DIM];
__device__ __nv_bfloat16 g_wphi[(size_t)DIM * DIM];
__device__ __nv_bfloat16 g_wplo[(size_t)DIM * DIM];

// ---------------------------------------------------------------------------
// PTX helpers (sm_80-compatible only: cp.async, ldmatrix, mma.sync)
// ---------------------------------------------------------------------------
__device__ __forceinline__ uint32_t smem_u32(const void* p) {
    uint32_t a;
    asm("{ .reg .u64 t; cvta.to.shared.u64 t, %1; cvt.u32.u64 %0, t; }" : "=r"(a) : "l"(p));
    return a;
}

#define CP_ASYNC16(dst, src) \
    asm volatile("cp.async.cg.shared.global [%0], [%1], 16;" :: "r"(dst), "l"(src))
#define CP_COMMIT() asm volatile("cp.async.commit_group;" ::: "memory")
#define CP_WAIT1()  asm volatile("cp.async.wait_group 1;" ::: "memory")

#define LDSM_X4(r0, r1, r2, r3, addr) \
    asm volatile("ldmatrix.sync.aligned.m8n8.x4.shared.b16 {%0,%1,%2,%3}, [%4];" \
        : "=r"(r0), "=r"(r1), "=r"(r2), "=r"(r3) : "r"(addr))

#define MMA16816(d, a, b) \
    asm volatile("mma.sync.aligned.m16n8k16.row.col.f32.bf16.bf16.f32 " \
        "{%0,%1,%2,%3}, {%4,%5,%6,%7}, {%8,%9}, {%0,%1,%2,%3};" \
        : "+f"((d)[0]), "+f"((d)[1]), "+f"((d)[2]), "+f"((d)[3]) \
        : "r"((a)[0]), "r"((a)[1]), "r"((a)[2]), "r"((a)[3]), \
          "r"((b)[0]), "r"((b)[1]))

// ---------------------------------------------------------------------------
// Split kernel: fp32 -> (bf16 hi, bf16 lo)
// ---------------------------------------------------------------------------
__global__ void split_bf16(const float* __restrict__ src,
                           __nv_bfloat16* __restrict__ hi,
                           __nv_bfloat16* __restrict__ lo, int n4)
{
    int i = blockIdx.x * blockDim.x + threadIdx.x;
    if (i >= n4) return;
    float4 v = ((const float4*)src)[i];
    float hx = __bfloat162float(__float2bfloat16_rn(v.x));
    float hy = __bfloat162float(__float2bfloat16_rn(v.y));
    float hz = __bfloat162float(__float2bfloat16_rn(v.z));
    float hw = __bfloat162float(__float2bfloat16_rn(v.w));
    __nv_bfloat162* H = (__nv_bfloat162*)hi;
    __nv_bfloat162* L = (__nv_bfloat162*)lo;
    H[2 * i]     = __floats2bfloat162_rn(v.x, v.y);
    H[2 * i + 1] = __floats2bfloat162_rn(v.z, v.w);
    L[2 * i]     = __floats2bfloat162_rn(v.x - hx, v.y - hy);
    L[2 * i + 1] = __floats2bfloat162_rn(v.z - hz, v.w - hw);
}

// ---------------------------------------------------------------------------
// bf16x3 GEMM via mma.sync: C[M,N] = A[M,384] @ W[N,384]^T + bias
// A,W as bf16 hi/lo pairs, K-major. 128x128 tile, 256 thr, 3-stage cp.async.
// ---------------------------------------------------------------------------
#define BK        32
#define NCHUNK    (KTOT / BK)            // 12
#define NSTAGE    3
#define ASTRIDE   80                     // bytes per 32-bf16 row (64 + 16 pad)
#define HALF_B    (128 * ASTRIDE)        // 10240
#define STAGE_B   (4 * HALF_B)           // 40960  (Ahi|Alo|Bhi|Blo)
#define GEMM_SMEM (NSTAGE * STAGE_B)     // 122880

__global__ void __launch_bounds__(256) gemm_bf16x3(
    const __nv_bfloat16* __restrict__ Ahi, const __nv_bfloat16* __restrict__ Alo,
    const __nv_bfloat16* __restrict__ Bhi, const __nv_bfloat16* __restrict__ Blo,
    const float* __restrict__ bias, float* __restrict__ C, int N)
{
    extern __shared__ char smem[];
    const uint32_t sb = smem_u32(smem);
    const int tid  = threadIdx.x;
    const int lane = tid & 31;
    const int wid  = tid >> 5;
    const int warp_m = wid & 1;          // 2 row-warps  (64 rows each)
    const int warp_n = wid >> 1;         // 4 col-warps  (32 cols each)
    const int bm = blockIdx.y * 128;
    const int bn = blockIdx.x * 128;

    float acc[4][4][4];
    #pragma unroll
    for (int i = 0; i < 4; ++i)
        #pragma unroll
        for (int j = 0; j < 4; ++j)
            #pragma unroll
            for (int r = 0; r < 4; ++r) acc[i][j][r] = 0.0f;

    const __nv_bfloat16* srcs[4] = {Ahi, Alo, Bhi, Blo};

    // Load one k32 chunk into a stage: 4 operand-halves, 512 x 16B each.
    auto load_chunk = [&](int stage, int kc) {
        #pragma unroll
        for (int t = 0; t < 4; ++t) {
            const __nv_bfloat16* src = srcs[t];
            const int rbase = (t < 2) ? bm : bn;
            const uint32_t hoff = sb + (uint32_t)stage * STAGE_B + (uint32_t)t * HALF_B;
            #pragma unroll
            for (int it = 0; it < 2; ++it) {
                int idx = tid + it * 256;
                int row = idx >> 2;
                int c16 = idx & 3;
                const __nv_bfloat16* g = src + (size_t)(rbase + row) * KTOT + kc + c16 * 8;
                uint32_t dst = hoff + (uint32_t)(row * ASTRIDE + c16 * 16);
                CP_ASYNC16(dst, g);
            }
        }
    };

    // prologue: chunks 0,1,2 -> stages 0,1,2
    load_chunk(0, 0);      CP_COMMIT();
    load_chunk(1, BK);     CP_COMMIT();
    load_chunk(2, 2 * BK); CP_COMMIT();

    for (int c = 0; c < NCHUNK; ++c) {
        CP_WAIT1();
        __syncthreads();

        // prefetch chunk c+2 into stage freed by last iteration's compute
        if (c >= 1 && c + 2 < NCHUNK) load_chunk((c + 2) % NSTAGE, (c + 2) * BK);
        CP_COMMIT();

        const uint32_t base = sb + (uint32_t)(c % NSTAGE) * STAGE_B;
        #pragma unroll
        for (int ks = 0; ks < 2; ++ks) {
            const uint32_t koff = (uint32_t)(ks * 32) + ((lane >> 4) << 4);
            const uint32_t arow = (uint32_t)(warp_m * 64 + (lane & 15));
            const uint32_t brow = (uint32_t)(warp_n * 32 + (lane & 15));

            uint32_t ah[4][4], al[4][4], bh[4][2], bl[4][2];

            #pragma unroll
            for (int mf = 0; mf < 4; ++mf) {
                uint32_t a = base + (arow + mf * 16) * ASTRIDE + koff;
                LDSM_X4(ah[mf][0], ah[mf][1], ah[mf][2], ah[mf][3], a);
                LDSM_X4(al[mf][0], al[mf][1], al[mf][2], al[mf][3], a + HALF_B);
            }
            #pragma unroll
            for (int g = 0; g < 2; ++g) {
                uint32_t a = base + 2 * HALF_B + (brow + g * 16) * ASTRIDE + koff;
                uint32_t r0, r1, r2, r3;
                LDSM_X4(r0, r1, r2, r3, a);
                bh[2 * g][0] = r0; bh[2 * g][1] = r2;
                bh[2 * g + 1][0] = r1; bh[2 * g + 1][1] = r3;
                LDSM_X4(r0, r1, r2, r3, a + HALF_B);
                bl[2 * g][0] = r0; bl[2 * g][1] = r2;
                bl[2 * g + 1][0] = r1; bl[2 * g + 1][1] = r3;
            }

            #pragma unroll
            for (int mf = 0; mf < 4; ++mf)
                #pragma unroll
                for (int nf = 0; nf < 4; ++nf) {
                    MMA16816(acc[mf][nf], ah[mf], bh[nf]);
                    MMA16816(acc[mf][nf], ah[mf], bl[nf]);
                    MMA16816(acc[mf][nf], al[mf], bh[nf]);
                }
        }
    }

    // epilogue: bias add + fp32 store
    #pragma unroll
    for (int mf = 0; mf < 4; ++mf) {
        int row = bm + warp_m * 64 + mf * 16 + (lane >> 2);
        #pragma unroll
        for (int nf = 0; nf < 4; ++nf) {
            int col = bn + warp_n * 32 + nf * 8 + (lane & 3) * 2;
            float b0 = bias[col], b1 = bias[col + 1];
            float2 v0, v1;
            v0.x = acc[mf][nf][0] + b0; v0.y = acc[mf][nf][1] + b1;
            v1.x = acc[mf][nf][2] + b0; v1.y = acc[mf][nf][3] + b1;
            *(float2*)(C + (size_t)row * N + col)       = v0;
            *(float2*)(C + (size_t)(row + 8) * N + col) = v1;
        }
    }
}

// ---------------------------------------------------------------------------
// Attention: one CTA per (window b, head h). 128 threads.
// Writes ctx directly as bf16 hi/lo split (feeds the proj GEMM).
// ---------------------------------------------------------------------------
__global__ void __launch_bounds__(128) attn_kernel(
    const float* __restrict__ qkv,
    const float* __restrict__ rpb,
    const int*   __restrict__ ridx,
    __nv_bfloat16* __restrict__ ctx_hi, __nv_bfloat16* __restrict__ ctx_lo)
{
    const int b = blockIdx.x;
    const int h = blockIdx.y;
    const int tid = threadIdx.x;

    __shared__ float qs[N_TOK][HD + 1];
    __shared__ float ks[N_TOK][HD + 1];
    __shared__ float vs[N_TOK][HD + 1];
    __shared__ float s[N_TOK][51];

    for (int idx = tid; idx < N_TOK * (HD / 4); idx += 128) {
        int n  = idx >> 3;
        int d4 = (idx & 7) * 4;
        size_t base = ((size_t)(b * N_TOK + n)) * QKV_N + h * HD + d4;
        float4 q4 = *(const float4*)(qkv + base);
        float4 k4 = *(const float4*)(qkv + base + DIM);
        float4 v4 = *(const float4*)(qkv + base + 2 * DIM);
        qs[n][d4 + 0] = q4.x * SCALE; qs[n][d4 + 1] = q4.y * SCALE;
        qs[n][d4 + 2] = q4.z * SCALE; qs[n][d4 + 3] = q4.w * SCALE;
        ks[n][d4 + 0] = k4.x; ks[n][d4 + 1] = k4.y;
        ks[n][d4 + 2] = k4.z; ks[n][d4 + 3] = k4.w;
        vs[n][d4 + 0] = v4.x; vs[n][d4 + 1] = v4.y;
        vs[n][d4 + 2] = v4.z; vs[n][d4 + 3] = v4.w;
    }
    __syncthreads();

    for (int idx = tid; idx < N_TOK * N_TOK; idx += 128) {
        int i = idx / N_TOK, j = idx - i * N_TOK;
        float acc = rpb[ridx[idx] * HEADS + h];
        #pragma unroll
        for (int kk = 0; kk < HD; ++kk)
            acc = fmaf(qs[i][kk], ks[j][kk], acc);
        s[i][j] = acc;
    }
    __syncthreads();

    if (tid < N_TOK) {
        float m = -1e30f;
        #pragma unroll 7
        for (int j = 0; j < N_TOK; ++j) m = fmaxf(m, s[tid][j]);
        float sum = 0.0f;
        #pragma unroll 7
        for (int j = 0; j < N_TOK; ++j) {
            float e = __expf(s[tid][j] - m);
            s[tid][j] = e;
            sum += e;
        }
        float inv = 1.0f / sum;
        #pragma unroll 7
        for (int j = 0; j < N_TOK; ++j) s[tid][j] *= inv;
    }
    __syncthreads();

    for (int idx = tid; idx < N_TOK * HD; idx += 128) {
        int i = idx >> 5;
        int d = idx & 31;
        float acc = 0.0f;
        #pragma unroll
        for (int j = 0; j < N_TOK; ++j)
            acc = fmaf(s[i][j], vs[j][d], acc);
        size_t o = ((size_t)(b * N_TOK + i)) * DIM + h * HD + d;
        __nv_bfloat16 hbf = __float2bfloat16_rn(acc);
        ctx_hi[o] = hbf;
        ctx_lo[o] = __float2bfloat16_rn(acc - __bfloat162float(hbf));
    }
}

// ---------------------------------------------------------------------------
extern "C" void kernel_launch(void* const* d_in, const int* in_sizes, int n_in,
                              void* d_out, int out_size)
{
    const float* x      = (const float*)d_in[0];
    const float* qkv_w  = (const float*)d_in[1];
    const float* qkv_b  = (const float*)d_in[2];
    const float* proj_w = (const float*)d_in[3];
    const float* proj_b = (const float*)d_in[4];
    const float* rpb    = (const float*)d_in[5];
    const int*   ridx   = (const int*)d_in[6];
    float* out = (float*)d_out;

    __nv_bfloat16 *xhi, *xlo, *chi, *clo, *wqh, *wql, *wph, *wpl;
    float* qkv_s;
    cudaGetSymbolAddress((void**)&xhi,   g_xhi);
    cudaGetSymbolAddress((void**)&xlo,   g_xlo);
    cudaGetSymbolAddress((void**)&qkv_s, g_qkv);
    cudaGetSymbolAddress((void**)&chi,   g_chi);
    cudaGetSymbolAddress((void**)&clo,   g_clo);
    cudaGetSymbolAddress((void**)&wqh,   g_wqhi);
    cudaGetSymbolAddress((void**)&wql,   g_wqlo);
    cudaGetSymbolAddress((void**)&wph,   g_wphi);
    cudaGetSymbolAddress((void**)&wpl,   g_wplo);

    static bool attr_set = false;
    if (!attr_set) {
        cudaFuncSetAttribute(gemm_bf16x3, cudaFuncAttributeMaxDynamicSharedMemorySize, GEMM_SMEM);
        attr_set = true;
    }

    // 1) bf16 splits of x and weights
    {
        int n4 = (M_TOT * DIM) / 4;
        split_bf16<<<(n4 + 255) / 256, 256>>>(x, xhi, xlo, n4);
        int w4 = (QKV_N * DIM) / 4;
        split_bf16<<<(w4 + 255) / 256, 256>>>(qkv_w, wqh, wql, w4);
        int p4 = (DIM * DIM) / 4;
        split_bf16<<<(p4 + 255) / 256, 256>>>(proj_w, wph, wpl, p4);
    }

    // 2) QKV GEMM: [200704,384] @ [1152,384]^T -> fp32 [200704,1152]
    {
        dim3 grid(QKV_N / 128, M_TOT / 128);   // (9, 1568)
        gemm_bf16x3<<<grid, 256, GEMM_SMEM>>>(xhi, xlo, wqh, wql, qkv_b, qkv_s, QKV_N);
    }

    // 3) Attention (fused bf16 split of ctx)
    {
        dim3 grid(B_WIN, HEADS);
        attn_kernel<<<grid, 128>>>(qkv_s, rpb, ridx, chi, clo);
    }

    // 4) Projection GEMM: [200704,384] @ [384,384]^T -> out
    {
        dim3 grid(DIM / 128, M_TOT / 128);     // (3, 1568)
        gemm_bf16x3<<<grid, 256, GEMM_SMEM>>>(chi, clo, wph, wpl, proj_b, out, DIM);
    }
}

// round 5
// speedup vs baseline: 2.2478x; 1.4994x over previous
#include <cuda_runtime.h>
#include <cuda_bf16.h>
#include <cuda_fp16.h>
#include <math.h>
#include <stdint.h>

// Problem constants
#define B_WIN 4096
#define N_TOK 49
#define DIM   384
#define HEADS 12
#define HD    32
#define M_TOT (B_WIN * N_TOK)     // 200704
#define QKV_N (3 * DIM)           // 1152
#define KTOT  384
#define SCALE 0.17677669529663687f

// ---------------------------------------------------------------------------
// Scratch (static device globals — allocation-guard safe)
// ---------------------------------------------------------------------------
__device__ __nv_bfloat16 g_xhi[(size_t)M_TOT * DIM];
__device__ __nv_bfloat16 g_xlo[(size_t)M_TOT * DIM];
__device__ float         g_qkv[(size_t)M_TOT * QKV_N];
__device__ __nv_bfloat16 g_chi[(size_t)M_TOT * DIM];
__device__ __nv_bfloat16 g_clo[(size_t)M_TOT * DIM];
__device__ __nv_bfloat16 g_wqhi[(size_t)QKV_N * DIM];
__device__ __nv_bfloat16 g_wqlo[(size_t)QKV_N * DIM];
__device__ __nv_bfloat16 g_wphi[(size_t)DIM * DIM];
__device__ __nv_bfloat16 g_wplo[(size_t)DIM * DIM];
__device__ float         g_bias[HEADS * N_TOK * N_TOK];   // [12][49][49]

// ---------------------------------------------------------------------------
// PTX helpers (sm_80-compatible only)
// ---------------------------------------------------------------------------
__device__ __forceinline__ uint32_t smem_u32(const void* p) {
    uint32_t a;
    asm("{ .reg .u64 t; cvta.to.shared.u64 t, %1; cvt.u32.u64 %0, t; }" : "=r"(a) : "l"(p));
    return a;
}

#define CP_ASYNC16(dst, src) \
    asm volatile("cp.async.cg.shared.global [%0], [%1], 16;" :: "r"(dst), "l"(src))
#define CP_COMMIT() asm volatile("cp.async.commit_group;" ::: "memory")
#define CP_WAIT1()  asm volatile("cp.async.wait_group 1;" ::: "memory")

#define LDSM_X4(r0, r1, r2, r3, addr) \
    asm volatile("ldmatrix.sync.aligned.m8n8.x4.shared.b16 {%0,%1,%2,%3}, [%4];" \
        : "=r"(r0), "=r"(r1), "=r"(r2), "=r"(r3) : "r"(addr))

#define MMA_BF16(d, a, b) \
    asm volatile("mma.sync.aligned.m16n8k16.row.col.f32.bf16.bf16.f32 " \
        "{%0,%1,%2,%3}, {%4,%5,%6,%7}, {%8,%9}, {%0,%1,%2,%3};" \
        : "+f"((d)[0]), "+f"((d)[1]), "+f"((d)[2]), "+f"((d)[3]) \
        : "r"((a)[0]), "r"((a)[1]), "r"((a)[2]), "r"((a)[3]), \
          "r"((b)[0]), "r"((b)[1]))

#define MMA_F16(d, a, b) \
    asm volatile("mma.sync.aligned.m16n8k16.row.col.f32.f16.f16.f32 " \
        "{%0,%1,%2,%3}, {%4,%5,%6,%7}, {%8,%9}, {%0,%1,%2,%3};" \
        : "+f"((d)[0]), "+f"((d)[1]), "+f"((d)[2]), "+f"((d)[3]) \
        : "r"((a)[0]), "r"((a)[1]), "r"((a)[2]), "r"((a)[3]), \
          "r"((b)[0]), "r"((b)[1]))

// ---------------------------------------------------------------------------
// Bias precompute: g_bias[h][ij] = rpb[ridx[ij]*12 + h]
// ---------------------------------------------------------------------------
__global__ void bias_kernel(const float* __restrict__ rpb, const int* __restrict__ ridx,
                            float* __restrict__ bias)
{
    int h = blockIdx.x;
    for (int ij = threadIdx.x; ij < N_TOK * N_TOK; ij += blockDim.x)
        bias[h * N_TOK * N_TOK + ij] = rpb[ridx[ij] * HEADS + h];
}

// ---------------------------------------------------------------------------
// Split kernel: fp32 -> (bf16 hi, bf16 lo)
// ---------------------------------------------------------------------------
__global__ void split_bf16(const float* __restrict__ src,
                           __nv_bfloat16* __restrict__ hi,
                           __nv_bfloat16* __restrict__ lo, int n4)
{
    int i = blockIdx.x * blockDim.x + threadIdx.x;
    if (i >= n4) return;
    float4 v = ((const float4*)src)[i];
    float hx = __bfloat162float(__float2bfloat16_rn(v.x));
    float hy = __bfloat162float(__float2bfloat16_rn(v.y));
    float hz = __bfloat162float(__float2bfloat16_rn(v.z));
    float hw = __bfloat162float(__float2bfloat16_rn(v.w));
    __nv_bfloat162* H = (__nv_bfloat162*)hi;
    __nv_bfloat162* L = (__nv_bfloat162*)lo;
    H[2 * i]     = __floats2bfloat162_rn(v.x, v.y);
    H[2 * i + 1] = __floats2bfloat162_rn(v.z, v.w);
    L[2 * i]     = __floats2bfloat162_rn(v.x - hx, v.y - hy);
    L[2 * i + 1] = __floats2bfloat162_rn(v.z - hz, v.w - hw);
}

// ---------------------------------------------------------------------------
// bf16x3 GEMM: C[M,N] = A[M,384] @ W[N,384]^T + bias. fp32 out.
// 128x128 tile, 256 thr, 2-stage cp.async (2 CTAs/SM).
// ---------------------------------------------------------------------------
#define BK        32
#define NCHUNK    (KTOT / BK)            // 12
#define ASTRIDE   80                     // bytes per 32-bf16 row (64 + 16 pad)
#define HALF_B    (128 * ASTRIDE)        // 10240
#define STAGE_B   (4 * HALF_B)           // 40960
#define GEMM_SMEM (2 * STAGE_B)          // 81920

__global__ void __launch_bounds__(256, 2) gemm_bf16x3(
    const __nv_bfloat16* __restrict__ Ahi, const __nv_bfloat16* __restrict__ Alo,
    const __nv_bfloat16* __restrict__ Bhi, const __nv_bfloat16* __restrict__ Blo,
    const float* __restrict__ bias, float* __restrict__ C, int N)
{
    extern __shared__ char smem[];
    const uint32_t sb = smem_u32(smem);
    const int tid  = threadIdx.x;
    const int lane = tid & 31;
    const int wid  = tid >> 5;
    const int warp_m = wid & 1;
    const int warp_n = wid >> 1;
    const int bm = blockIdx.y * 128;
    const int bn = blockIdx.x * 128;

    float acc[4][4][4];
    #pragma unroll
    for (int i = 0; i < 4; ++i)
        #pragma unroll
        for (int j = 0; j < 4; ++j)
            #pragma unroll
            for (int r = 0; r < 4; ++r) acc[i][j][r] = 0.0f;

    const __nv_bfloat16* srcs[4] = {Ahi, Alo, Bhi, Blo};

    auto load_chunk = [&](int stage, int kc) {
        #pragma unroll
        for (int t = 0; t < 4; ++t) {
            const __nv_bfloat16* src = srcs[t];
            const int rbase = (t < 2) ? bm : bn;
            const uint32_t hoff = sb + (uint32_t)stage * STAGE_B + (uint32_t)t * HALF_B;
            #pragma unroll
            for (int it = 0; it < 2; ++it) {
                int idx = tid + it * 256;
                int row = idx >> 2;
                int c16 = idx & 3;
                const __nv_bfloat16* g = src + (size_t)(rbase + row) * KTOT + kc + c16 * 8;
                uint32_t dst = hoff + (uint32_t)(row * ASTRIDE + c16 * 16);
                CP_ASYNC16(dst, g);
            }
        }
    };

    load_chunk(0, 0);  CP_COMMIT();
    load_chunk(1, BK); CP_COMMIT();

    for (int c = 0; c < NCHUNK; ++c) {
        CP_WAIT1();
        __syncthreads();

        const uint32_t base = sb + (uint32_t)(c & 1) * STAGE_B;
        #pragma unroll
        for (int ks = 0; ks < 2; ++ks) {
            const uint32_t koff = (uint32_t)(ks * 32) + ((lane >> 4) << 4);
            const uint32_t arow = (uint32_t)(warp_m * 64 + (lane & 15));
            const uint32_t brow = (uint32_t)(warp_n * 32 + (lane & 15));

            uint32_t ah[4][4], al[4][4], bh[4][2], bl[4][2];
            #pragma unroll
            for (int mf = 0; mf < 4; ++mf) {
                uint32_t a = base + (arow + mf * 16) * ASTRIDE + koff;
                LDSM_X4(ah[mf][0], ah[mf][1], ah[mf][2], ah[mf][3], a);
                LDSM_X4(al[mf][0], al[mf][1], al[mf][2], al[mf][3], a + HALF_B);
            }
            #pragma unroll
            for (int g = 0; g < 2; ++g) {
                uint32_t a = base + 2 * HALF_B + (brow + g * 16) * ASTRIDE + koff;
                uint32_t r0, r1, r2, r3;
                LDSM_X4(r0, r1, r2, r3, a);
                bh[2 * g][0] = r0; bh[2 * g][1] = r2;
                bh[2 * g + 1][0] = r1; bh[2 * g + 1][1] = r3;
                LDSM_X4(r0, r1, r2, r3, a + HALF_B);
                bl[2 * g][0] = r0; bl[2 * g][1] = r2;
                bl[2 * g + 1][0] = r1; bl[2 * g + 1][1] = r3;
            }
            #pragma unroll
            for (int mf = 0; mf < 4; ++mf)
                #pragma unroll
                for (int nf = 0; nf < 4; ++nf) {
                    MMA_BF16(acc[mf][nf], ah[mf], bh[nf]);
                    MMA_BF16(acc[mf][nf], ah[mf], bl[nf]);
                    MMA_BF16(acc[mf][nf], al[mf], bh[nf]);
                }
        }
        __syncthreads();
        if (c + 2 < NCHUNK) load_chunk(c & 1, (c + 2) * BK);
        CP_COMMIT();
    }

    #pragma unroll
    for (int mf = 0; mf < 4; ++mf) {
        int row = bm + warp_m * 64 + mf * 16 + (lane >> 2);
        #pragma unroll
        for (int nf = 0; nf < 4; ++nf) {
            int col = bn + warp_n * 32 + nf * 8 + (lane & 3) * 2;
            float b0 = bias[col], b1 = bias[col + 1];
            *(float2*)(C + (size_t)row * N + col) =
                make_float2(acc[mf][nf][0] + b0, acc[mf][nf][1] + b1);
            *(float2*)(C + (size_t)(row + 8) * N + col) =
                make_float2(acc[mf][nf][2] + b0, acc[mf][nf][3] + b1);
        }
    }
}

// ---------------------------------------------------------------------------
// Tensorized attention, register-resident softmax.
// One CTA per (window b, head h), 128 threads (4 warps).
// Q,K fp16 in smem; V bf16 hi/lo transposed in smem.
// S = Q@K^T fragments stay in registers -> shuffle softmax -> P fragments
// (bf16 hi/lo) -> P@V 3-term mma. ctx written as bf16 hi/lo.
// ---------------------------------------------------------------------------
#define QK_STRIDE 40      // halves per row (32 data + 8 pad) = 80B
#define VT_STRIDE 72      // bf16 per row (64 data + 8 pad) = 144B

__global__ void __launch_bounds__(128) attn_kernel(
    const float* __restrict__ qkv,
    const float* __restrict__ bias_mat,
    __nv_bfloat16* __restrict__ ctx_hi, __nv_bfloat16* __restrict__ ctx_lo)
{
    const int b = blockIdx.x;
    const int h = blockIdx.y;
    const int tid = threadIdx.x;
    const int lane = tid & 31;
    const int w = tid >> 5;

    __shared__ __half        qs[64 * QK_STRIDE];   // 5120B
    __shared__ __half        ks[64 * QK_STRIDE];   // 5120B
    __shared__ __nv_bfloat16 vth[32 * VT_STRIDE];  // 4608B
    __shared__ __nv_bfloat16 vtl[32 * VT_STRIDE];  // 4608B

    // zero init (pads + tail rows/cols)
    for (int i = tid; i < 64 * QK_STRIDE / 2; i += 128) {
        ((uint32_t*)qs)[i] = 0;
        ((uint32_t*)ks)[i] = 0;
    }
    for (int i = tid; i < 32 * VT_STRIDE / 2; i += 128) {
        ((uint32_t*)vth)[i] = 0;
        ((uint32_t*)vtl)[i] = 0;
    }
    __syncthreads();

    // load q,k (fp16); v transposed (bf16 hi/lo)
    for (int idx = tid; idx < N_TOK * 12; idx += 128) {
        int n  = idx / 12;
        int r  = idx % 12;
        int t  = r >> 2;
        int c8 = (r & 3) * 8;
        const float* src = qkv + (size_t)(b * N_TOK + n) * QKV_N + h * HD + t * DIM + c8;
        float4 v0 = *(const float4*)src;
        float4 v1 = *(const float4*)(src + 4);
        if (t < 2) {
            __half* dst = (t == 0 ? qs : ks) + n * QK_STRIDE + c8;
            ((__half2*)dst)[0] = __floats2half2_rn(v0.x, v0.y);
            ((__half2*)dst)[1] = __floats2half2_rn(v0.z, v0.w);
            ((__half2*)dst)[2] = __floats2half2_rn(v1.x, v1.y);
            ((__half2*)dst)[3] = __floats2half2_rn(v1.z, v1.w);
        } else {
            float f[8] = {v0.x, v0.y, v0.z, v0.w, v1.x, v1.y, v1.z, v1.w};
            #pragma unroll
            for (int e = 0; e < 8; ++e) {
                __nv_bfloat16 hi = __float2bfloat16_rn(f[e]);
                vth[(c8 + e) * VT_STRIDE + n] = hi;
                vtl[(c8 + e) * VT_STRIDE + n] = __float2bfloat16_rn(f[e] - __bfloat162float(hi));
            }
        }
    }
    __syncthreads();

    const uint32_t qb  = smem_u32(qs);
    const uint32_t kb  = smem_u32(ks);
    const uint32_t vhb = smem_u32(vth);
    const uint32_t vlb = smem_u32(vtl);
    const int lrow = lane & 15;
    const int khi  = (lane >> 4) * 16;   // bytes

    // ---- S = Q @ K^T (per warp: rows w*16..+15, all 64 key cols) ----
    float accS[8][4];
    #pragma unroll
    for (int nf = 0; nf < 8; ++nf)
        #pragma unroll
        for (int r = 0; r < 4; ++r) accS[nf][r] = 0.0f;

    #pragma unroll
    for (int ki = 0; ki < 2; ++ki) {
        const uint32_t koff = ki * 32 + khi;
        uint32_t a[4];
        LDSM_X4(a[0], a[1], a[2], a[3], qb + (w * 16 + lrow) * (QK_STRIDE * 2) + koff);
        uint32_t bfr[8][2];
        #pragma unroll
        for (int g = 0; g < 4; ++g) {
            uint32_t r0, r1, r2, r3;
            LDSM_X4(r0, r1, r2, r3, kb + (g * 16 + lrow) * (QK_STRIDE * 2) + koff);
            bfr[2 * g][0] = r0; bfr[2 * g][1] = r2;
            bfr[2 * g + 1][0] = r1; bfr[2 * g + 1][1] = r3;
        }
        #pragma unroll
        for (int nf = 0; nf < 8; ++nf) MMA_F16(accS[nf], a, bfr[nf]);
    }

    // ---- register softmax ----
    // fragment rows: rA = w*16 + lane/4 (regs 0,1), rB = rA+8 (regs 2,3)
    // fragment cols: nf*8 + (lane&3)*2 + {0,1}
    const int rA = w * 16 + (lane >> 2);
    const int rB = rA + 8;
    const int c0 = (lane & 3) * 2;
    const float* bh = bias_mat + h * N_TOK * N_TOK;

    #pragma unroll
    for (int nf = 0; nf < 8; ++nf) {
        #pragma unroll
        for (int j = 0; j < 4; ++j) {
            int row = (j < 2) ? rA : rB;
            int col = nf * 8 + c0 + (j & 1);
            if (row < N_TOK && col < N_TOK)
                accS[nf][j] = accS[nf][j] * SCALE + bh[row * N_TOK + col];
            else
                accS[nf][j] = -1e30f;
        }
    }
    float mA = -1e30f, mB = -1e30f;
    #pragma unroll
    for (int nf = 0; nf < 8; ++nf) {
        mA = fmaxf(mA, fmaxf(accS[nf][0], accS[nf][1]));
        mB = fmaxf(mB, fmaxf(accS[nf][2], accS[nf][3]));
    }
    mA = fmaxf(mA, __shfl_xor_sync(0xFFFFFFFF, mA, 1));
    mA = fmaxf(mA, __shfl_xor_sync(0xFFFFFFFF, mA, 2));
    mB = fmaxf(mB, __shfl_xor_sync(0xFFFFFFFF, mB, 1));
    mB = fmaxf(mB, __shfl_xor_sync(0xFFFFFFFF, mB, 2));

    float sA = 0.0f, sB = 0.0f;
    #pragma unroll
    for (int nf = 0; nf < 8; ++nf) {
        #pragma unroll
        for (int j = 0; j < 4; ++j) {
            float m = (j < 2) ? mA : mB;
            float e = (accS[nf][j] > -1e29f) ? __expf(accS[nf][j] - m) : 0.0f;
            accS[nf][j] = e;
            if (j < 2) sA += e; else sB += e;
        }
    }
    sA += __shfl_xor_sync(0xFFFFFFFF, sA, 1);
    sA += __shfl_xor_sync(0xFFFFFFFF, sA, 2);
    sB += __shfl_xor_sync(0xFFFFFFFF, sB, 1);
    sB += __shfl_xor_sync(0xFFFFFFFF, sB, 2);
    const float invA = 1.0f / fmaxf(sA, 1e-30f);
    const float invB = 1.0f / fmaxf(sB, 1e-30f);
    #pragma unroll
    for (int nf = 0; nf < 8; ++nf) {
        accS[nf][0] *= invA; accS[nf][1] *= invA;
        accS[nf][2] *= invB; accS[nf][3] *= invB;
    }

    // ---- out = P @ V (P fragments from registers, bf16 hi/lo x3) ----
    float accO[4][4];
    #pragma unroll
    for (int nf = 0; nf < 4; ++nf)
        #pragma unroll
        for (int r = 0; r < 4; ++r) accO[nf][r] = 0.0f;

    #pragma unroll
    for (int kt = 0; kt < 4; ++kt) {
        // pack A fragments: a0={tile 2kt, j0,j1}, a1={tile 2kt, j2,j3},
        //                   a2={tile 2kt+1, j0,j1}, a3={tile 2kt+1, j2,j3}
        uint32_t aph[4], apl[4];
        #pragma unroll
        for (int q = 0; q < 4; ++q) {
            const int nf = 2 * kt + (q >> 1);
            const int j0 = (q & 1) * 2;
            float p0 = accS[nf][j0], p1 = accS[nf][j0 + 1];
            __nv_bfloat162 hi2 = __floats2bfloat162_rn(p0, p1);
            __nv_bfloat162 lo2 = __floats2bfloat162_rn(
                p0 - __bfloat162float(hi2.x), p1 - __bfloat162float(hi2.y));
            aph[q] = *(uint32_t*)&hi2;
            apl[q] = *(uint32_t*)&lo2;
        }
        const uint32_t koff = kt * 32 + khi;
        uint32_t bvh[4][2], bvl[4][2];
        #pragma unroll
        for (int g = 0; g < 2; ++g) {
            uint32_t off = (g * 16 + lrow) * (VT_STRIDE * 2) + koff;
            uint32_t r0, r1, r2, r3;
            LDSM_X4(r0, r1, r2, r3, vhb + off);
            bvh[2 * g][0] = r0; bvh[2 * g][1] = r2;
            bvh[2 * g + 1][0] = r1; bvh[2 * g + 1][1] = r3;
            LDSM_X4(r0, r1, r2, r3, vlb + off);
            bvl[2 * g][0] = r0; bvl[2 * g][1] = r2;
            bvl[2 * g + 1][0] = r1; bvl[2 * g + 1][1] = r3;
        }
        #pragma unroll
        for (int nf = 0; nf < 4; ++nf) {
            MMA_BF16(accO[nf], aph, bvh[nf]);
            MMA_BF16(accO[nf], aph, bvl[nf]);
            MMA_BF16(accO[nf], apl, bvh[nf]);
        }
    }

    // epilogue: bf16 hi/lo split of ctx
    #pragma unroll
    for (int half_i = 0; half_i < 2; ++half_i) {
        int row = (half_i == 0) ? rA : rB;
        if (row < N_TOK) {
            size_t obase = (size_t)(b * N_TOK + row) * DIM + h * HD;
            #pragma unroll
            for (int nf = 0; nf < 4; ++nf) {
                int d = nf * 8 + c0;
                float v0 = accO[nf][2 * half_i + 0];
                float v1 = accO[nf][2 * half_i + 1];
                __nv_bfloat162 hi2 = __floats2bfloat162_rn(v0, v1);
                __nv_bfloat162 lo2 = __floats2bfloat162_rn(
                    v0 - __bfloat162float(hi2.x), v1 - __bfloat162float(hi2.y));
                *(__nv_bfloat162*)(ctx_hi + obase + d) = hi2;
                *(__nv_bfloat162*)(ctx_lo + obase + d) = lo2;
            }
        }
    }
}

// ---------------------------------------------------------------------------
extern "C" void kernel_launch(void* const* d_in, const int* in_sizes, int n_in,
                              void* d_out, int out_size)
{
    const float* x      = (const float*)d_in[0];
    const float* qkv_w  = (const float*)d_in[1];
    const float* qkv_b  = (const float*)d_in[2];
    const float* proj_w = (const float*)d_in[3];
    const float* proj_b = (const float*)d_in[4];
    const float* rpb    = (const float*)d_in[5];
    const int*   ridx   = (const int*)d_in[6];
    float* out = (float*)d_out;

    __nv_bfloat16 *xhi, *xlo, *chi, *clo, *wqh, *wql, *wph, *wpl;
    float *qkv_s, *biasm;
    cudaGetSymbolAddress((void**)&xhi,   g_xhi);
    cudaGetSymbolAddress((void**)&xlo,   g_xlo);
    cudaGetSymbolAddress((void**)&qkv_s, g_qkv);
    cudaGetSymbolAddress((void**)&chi,   g_chi);
    cudaGetSymbolAddress((void**)&clo,   g_clo);
    cudaGetSymbolAddress((void**)&wqh,   g_wqhi);
    cudaGetSymbolAddress((void**)&wql,   g_wqlo);
    cudaGetSymbolAddress((void**)&wph,   g_wphi);
    cudaGetSymbolAddress((void**)&wpl,   g_wplo);
    cudaGetSymbolAddress((void**)&biasm, g_bias);

    static bool attr_set = false;
    if (!attr_set) {
        cudaFuncSetAttribute(gemm_bf16x3, cudaFuncAttributeMaxDynamicSharedMemorySize, GEMM_SMEM);
        attr_set = true;
    }

    // 0) bias table
    bias_kernel<<<HEADS, 256>>>(rpb, ridx, biasm);

    // 1) bf16 splits
    {
        int n4 = (M_TOT * DIM) / 4;
        split_bf16<<<(n4 + 255) / 256, 256>>>(x, xhi, xlo, n4);
        int w4 = (QKV_N * DIM) / 4;
        split_bf16<<<(w4 + 255) / 256, 256>>>(qkv_w, wqh, wql, w4);
        int p4 = (DIM * DIM) / 4;
        split_bf16<<<(p4 + 255) / 256, 256>>>(proj_w, wph, wpl, p4);
    }

    // 2) QKV GEMM -> fp32 qkv
    {
        dim3 grid(QKV_N / 128, M_TOT / 128);   // (9, 1568)
        gemm_bf16x3<<<grid, 256, GEMM_SMEM>>>(xhi, xlo, wqh, wql, qkv_b, qkv_s, QKV_N);
    }

    // 3) Attention (tensor-core, register softmax, fused bf16 split of ctx)
    {
        dim3 grid(B_WIN, HEADS);
        attn_kernel<<<grid, 128>>>(qkv_s, biasm, chi, clo);
    }

    // 4) Projection GEMM -> fp32 out
    {
        dim3 grid(DIM / 128, M_TOT / 128);     // (3, 1568)
        gemm_bf16x3<<<grid, 256, GEMM_SMEM>>>(chi, clo, wph, wpl, proj_b, out, DIM);
    }
}

// round 6
// speedup vs baseline: 2.7599x; 1.2278x over previous
#include <cuda_runtime.h>
#include <cuda_bf16.h>
#include <cuda_fp16.h>
#include <math.h>
#include <stdint.h>

// Problem constants
#define B_WIN 4096
#define N_TOK 49
#define DIM   384
#define HEADS 12
#define HD    32
#define M_TOT (B_WIN * N_TOK)     // 200704
#define QKV_N (3 * DIM)           // 1152
#define KTOT  384
#define SCALE 0.17677669529663687f

// ---------------------------------------------------------------------------
// Scratch (static device globals — allocation-guard safe)
// ---------------------------------------------------------------------------
__device__ __half  g_xh [(size_t)M_TOT * DIM];
__device__ float   g_qkv[(size_t)M_TOT * QKV_N];
__device__ __half  g_chi[(size_t)M_TOT * DIM];
__device__ __half  g_clo[(size_t)M_TOT * DIM];
__device__ __half  g_wqh[(size_t)QKV_N * DIM];
__device__ __half  g_wql[(size_t)QKV_N * DIM];
__device__ __half  g_wph[(size_t)DIM * DIM];
__device__ __half  g_wpl[(size_t)DIM * DIM];
__device__ float   g_bias[HEADS * N_TOK * N_TOK];   // [12][49][49]

// ---------------------------------------------------------------------------
// PTX helpers (sm_80-compatible only)
// ---------------------------------------------------------------------------
__device__ __forceinline__ uint32_t smem_u32(const void* p) {
    uint32_t a;
    asm("{ .reg .u64 t; cvta.to.shared.u64 t, %1; cvt.u32.u64 %0, t; }" : "=r"(a) : "l"(p));
    return a;
}

#define CP_ASYNC16(dst, src) \
    asm volatile("cp.async.cg.shared.global [%0], [%1], 16;" :: "r"(dst), "l"(src))
#define CP_COMMIT() asm volatile("cp.async.commit_group;" ::: "memory")
#define CP_WAIT1()  asm volatile("cp.async.wait_group 1;" ::: "memory")

#define LDSM_X4(r0, r1, r2, r3, addr) \
    asm volatile("ldmatrix.sync.aligned.m8n8.x4.shared.b16 {%0,%1,%2,%3}, [%4];" \
        : "=r"(r0), "=r"(r1), "=r"(r2), "=r"(r3) : "r"(addr))

#define MMA_BF16(d, a, b) \
    asm volatile("mma.sync.aligned.m16n8k16.row.col.f32.bf16.bf16.f32 " \
        "{%0,%1,%2,%3}, {%4,%5,%6,%7}, {%8,%9}, {%0,%1,%2,%3};" \
        : "+f"((d)[0]), "+f"((d)[1]), "+f"((d)[2]), "+f"((d)[3]) \
        : "r"((a)[0]), "r"((a)[1]), "r"((a)[2]), "r"((a)[3]), \
          "r"((b)[0]), "r"((b)[1]))

#define MMA_F16(d, a, b) \
    asm volatile("mma.sync.aligned.m16n8k16.row.col.f32.f16.f16.f32 " \
        "{%0,%1,%2,%3}, {%4,%5,%6,%7}, {%8,%9}, {%0,%1,%2,%3};" \
        : "+f"((d)[0]), "+f"((d)[1]), "+f"((d)[2]), "+f"((d)[3]) \
        : "r"((a)[0]), "r"((a)[1]), "r"((a)[2]), "r"((a)[3]), \
          "r"((b)[0]), "r"((b)[1]))

// ---------------------------------------------------------------------------
// Bias precompute: g_bias[h][ij] = rpb[ridx[ij]*12 + h]
// ---------------------------------------------------------------------------
__global__ void bias_kernel(const float* __restrict__ rpb, const int* __restrict__ ridx,
                            float* __restrict__ bias)
{
    int h = blockIdx.x;
    for (int ij = threadIdx.x; ij < N_TOK * N_TOK; ij += blockDim.x)
        bias[h * N_TOK * N_TOK + ij] = rpb[ridx[ij] * HEADS + h];
}

// ---------------------------------------------------------------------------
// Splits
// ---------------------------------------------------------------------------
__global__ void split_h1(const float* __restrict__ src, __half* __restrict__ dst, int n4)
{
    int i = blockIdx.x * blockDim.x + threadIdx.x;
    if (i >= n4) return;
    float4 v = ((const float4*)src)[i];
    __half2* D = (__half2*)dst;
    D[2 * i]     = __floats2half2_rn(v.x, v.y);
    D[2 * i + 1] = __floats2half2_rn(v.z, v.w);
}

__global__ void split_h2(const float* __restrict__ src,
                         __half* __restrict__ hi, __half* __restrict__ lo, int n4)
{
    int i = blockIdx.x * blockDim.x + threadIdx.x;
    if (i >= n4) return;
    float4 v = ((const float4*)src)[i];
    __half2 h0 = __floats2half2_rn(v.x, v.y);
    __half2 h1 = __floats2half2_rn(v.z, v.w);
    __half2 l0 = __floats2half2_rn(v.x - __half2float(h0.x), v.y - __half2float(h0.y));
    __half2 l1 = __floats2half2_rn(v.z - __half2float(h1.x), v.w - __half2float(h1.y));
    ((__half2*)hi)[2 * i] = h0; ((__half2*)hi)[2 * i + 1] = h1;
    ((__half2*)lo)[2 * i] = l0; ((__half2*)lo)[2 * i + 1] = l1;
}

// ---------------------------------------------------------------------------
// fp16 split GEMM: C[M,N] = A[M,384] @ W[N,384]^T + bias (fp32 out).
// THREE=false: A single fp16 (Al unused), 2 mma terms  (QKV)
// THREE=true : A fp16 hi/lo, 3 mma terms               (proj)
// 128x128 tile, 256 thr, 2-stage cp.async.
// ---------------------------------------------------------------------------
#define BK        32
#define NCHUNK    (KTOT / BK)            // 12
#define ASTRIDE   80                     // bytes per 32-half row (64 + 16 pad)
#define HALF_B    (128 * ASTRIDE)        // 10240

template<bool THREE>
__global__ void __launch_bounds__(256, 2) gemm_f16(
    const __half* __restrict__ Ah, const __half* __restrict__ Al,
    const __half* __restrict__ Bh, const __half* __restrict__ Bl,
    const float* __restrict__ bias, float* __restrict__ C, int N)
{
    constexpr int NOPS    = THREE ? 4 : 3;
    constexpr int STAGE_B = NOPS * HALF_B;

    extern __shared__ char smem[];
    const uint32_t sb = smem_u32(smem);
    const int tid  = threadIdx.x;
    const int lane = tid & 31;
    const int wid  = tid >> 5;
    const int warp_m = wid & 1;
    const int warp_n = wid >> 1;
    const int bm = blockIdx.y * 128;
    const int bn = blockIdx.x * 128;

    float acc[4][4][4];
    #pragma unroll
    for (int i = 0; i < 4; ++i)
        #pragma unroll
        for (int j = 0; j < 4; ++j)
            #pragma unroll
            for (int r = 0; r < 4; ++r) acc[i][j][r] = 0.0f;

    // operand table: [Ah, (Al), Bh, Bl]
    const __half* srcs[4];
    srcs[0] = Ah;
    if (THREE) { srcs[1] = Al; srcs[2] = Bh; srcs[3] = Bl; }
    else       { srcs[1] = Bh; srcs[2] = Bl; srcs[3] = nullptr; }
    const int nA = THREE ? 2 : 1;   // operands on the A side

    auto load_chunk = [&](int stage, int kc) {
        #pragma unroll
        for (int t = 0; t < NOPS; ++t) {
            const __half* src = srcs[t];
            const int rbase = (t < nA) ? bm : bn;
            const uint32_t hoff = sb + (uint32_t)stage * STAGE_B + (uint32_t)t * HALF_B;
            #pragma unroll
            for (int it = 0; it < 2; ++it) {
                int idx = tid + it * 256;
                int row = idx >> 2;
                int c16 = idx & 3;
                const __half* g = src + (size_t)(rbase + row) * KTOT + kc + c16 * 8;
                uint32_t dst = hoff + (uint32_t)(row * ASTRIDE + c16 * 16);
                CP_ASYNC16(dst, g);
            }
        }
    };

    load_chunk(0, 0);  CP_COMMIT();
    load_chunk(1, BK); CP_COMMIT();

    const uint32_t bOff = (uint32_t)(nA * HALF_B);   // offset of Bh within stage

    for (int c = 0; c < NCHUNK; ++c) {
        CP_WAIT1();
        __syncthreads();

        const uint32_t base = sb + (uint32_t)(c & 1) * STAGE_B;
        #pragma unroll
        for (int ks = 0; ks < 2; ++ks) {
            const uint32_t koff = (uint32_t)(ks * 32) + ((lane >> 4) << 4);
            const uint32_t arow = (uint32_t)(warp_m * 64 + (lane & 15));
            const uint32_t brow = (uint32_t)(warp_n * 32 + (lane & 15));

            uint32_t ah[4][4], al[4][4], bh[4][2], bl[4][2];
            #pragma unroll
            for (int mf = 0; mf < 4; ++mf) {
                uint32_t a = base + (arow + mf * 16) * ASTRIDE + koff;
                LDSM_X4(ah[mf][0], ah[mf][1], ah[mf][2], ah[mf][3], a);
                if (THREE)
                    LDSM_X4(al[mf][0], al[mf][1], al[mf][2], al[mf][3], a + HALF_B);
            }
            #pragma unroll
            for (int g = 0; g < 2; ++g) {
                uint32_t a = base + bOff + (brow + g * 16) * ASTRIDE + koff;
                uint32_t r0, r1, r2, r3;
                LDSM_X4(r0, r1, r2, r3, a);
                bh[2 * g][0] = r0; bh[2 * g][1] = r2;
                bh[2 * g + 1][0] = r1; bh[2 * g + 1][1] = r3;
                LDSM_X4(r0, r1, r2, r3, a + HALF_B);
                bl[2 * g][0] = r0; bl[2 * g][1] = r2;
                bl[2 * g + 1][0] = r1; bl[2 * g + 1][1] = r3;
            }
            #pragma unroll
            for (int mf = 0; mf < 4; ++mf)
                #pragma unroll
                for (int nf = 0; nf < 4; ++nf) {
                    MMA_F16(acc[mf][nf], ah[mf], bh[nf]);
                    MMA_F16(acc[mf][nf], ah[mf], bl[nf]);
                    if (THREE) MMA_F16(acc[mf][nf], al[mf], bh[nf]);
                }
        }
        __syncthreads();
        if (c + 2 < NCHUNK) load_chunk(c & 1, (c + 2) * BK);
        CP_COMMIT();
    }

    #pragma unroll
    for (int mf = 0; mf < 4; ++mf) {
        int row = bm + warp_m * 64 + mf * 16 + (lane >> 2);
        #pragma unroll
        for (int nf = 0; nf < 4; ++nf) {
            int col = bn + warp_n * 32 + nf * 8 + (lane & 3) * 2;
            float b0 = bias[col], b1 = bias[col + 1];
            *(float2*)(C + (size_t)row * N + col) =
                make_float2(acc[mf][nf][0] + b0, acc[mf][nf][1] + b1);
            *(float2*)(C + (size_t)(row + 8) * N + col) =
                make_float2(acc[mf][nf][2] + b0, acc[mf][nf][3] + b1);
        }
    }
}

// ---------------------------------------------------------------------------
// Tensorized attention, register-resident softmax (validated in R5).
// Epilogue now writes ctx as fp16 hi/lo (feeds the 3-term fp16 proj GEMM).
// ---------------------------------------------------------------------------
#define QK_STRIDE 40      // halves per row (32 data + 8 pad) = 80B
#define VT_STRIDE 72      // bf16 per row (64 data + 8 pad) = 144B

__global__ void __launch_bounds__(128) attn_kernel(
    const float* __restrict__ qkv,
    const float* __restrict__ bias_mat,
    __half* __restrict__ ctx_hi, __half* __restrict__ ctx_lo)
{
    const int b = blockIdx.x;
    const int h = blockIdx.y;
    const int tid = threadIdx.x;
    const int lane = tid & 31;
    const int w = tid >> 5;

    __shared__ __half        qs[64 * QK_STRIDE];
    __shared__ __half        ks[64 * QK_STRIDE];
    __shared__ __nv_bfloat16 vth[32 * VT_STRIDE];
    __shared__ __nv_bfloat16 vtl[32 * VT_STRIDE];

    for (int i = tid; i < 64 * QK_STRIDE / 2; i += 128) {
        ((uint32_t*)qs)[i] = 0;
        ((uint32_t*)ks)[i] = 0;
    }
    for (int i = tid; i < 32 * VT_STRIDE / 2; i += 128) {
        ((uint32_t*)vth)[i] = 0;
        ((uint32_t*)vtl)[i] = 0;
    }
    __syncthreads();

    for (int idx = tid; idx < N_TOK * 12; idx += 128) {
        int n  = idx / 12;
        int r  = idx % 12;
        int t  = r >> 2;
        int c8 = (r & 3) * 8;
        const float* src = qkv + (size_t)(b * N_TOK + n) * QKV_N + h * HD + t * DIM + c8;
        float4 v0 = *(const float4*)src;
        float4 v1 = *(const float4*)(src + 4);
        if (t < 2) {
            __half* dst = (t == 0 ? qs : ks) + n * QK_STRIDE + c8;
            ((__half2*)dst)[0] = __floats2half2_rn(v0.x, v0.y);
            ((__half2*)dst)[1] = __floats2half2_rn(v0.z, v0.w);
            ((__half2*)dst)[2] = __floats2half2_rn(v1.x, v1.y);
            ((__half2*)dst)[3] = __floats2half2_rn(v1.z, v1.w);
        } else {
            float f[8] = {v0.x, v0.y, v0.z, v0.w, v1.x, v1.y, v1.z, v1.w};
            #pragma unroll
            for (int e = 0; e < 8; ++e) {
                __nv_bfloat16 hi = __float2bfloat16_rn(f[e]);
                vth[(c8 + e) * VT_STRIDE + n] = hi;
                vtl[(c8 + e) * VT_STRIDE + n] = __float2bfloat16_rn(f[e] - __bfloat162float(hi));
            }
        }
    }
    __syncthreads();

    const uint32_t qb  = smem_u32(qs);
    const uint32_t kb  = smem_u32(ks);
    const uint32_t vhb = smem_u32(vth);
    const uint32_t vlb = smem_u32(vtl);
    const int lrow = lane & 15;
    const int khi  = (lane >> 4) * 16;

    float accS[8][4];
    #pragma unroll
    for (int nf = 0; nf < 8; ++nf)
        #pragma unroll
        for (int r = 0; r < 4; ++r) accS[nf][r] = 0.0f;

    #pragma unroll
    for (int ki = 0; ki < 2; ++ki) {
        const uint32_t koff = ki * 32 + khi;
        uint32_t a[4];
        LDSM_X4(a[0], a[1], a[2], a[3], qb + (w * 16 + lrow) * (QK_STRIDE * 2) + koff);
        uint32_t bfr[8][2];
        #pragma unroll
        for (int g = 0; g < 4; ++g) {
            uint32_t r0, r1, r2, r3;
            LDSM_X4(r0, r1, r2, r3, kb + (g * 16 + lrow) * (QK_STRIDE * 2) + koff);
            bfr[2 * g][0] = r0; bfr[2 * g][1] = r2;
            bfr[2 * g + 1][0] = r1; bfr[2 * g + 1][1] = r3;
        }
        #pragma unroll
        for (int nf = 0; nf < 8; ++nf) MMA_F16(accS[nf], a, bfr[nf]);
    }

    const int rA = w * 16 + (lane >> 2);
    const int rB = rA + 8;
    const int c0 = (lane & 3) * 2;
    const float* bh = bias_mat + h * N_TOK * N_TOK;

    #pragma unroll
    for (int nf = 0; nf < 8; ++nf) {
        #pragma unroll
        for (int j = 0; j < 4; ++j) {
            int row = (j < 2) ? rA : rB;
            int col = nf * 8 + c0 + (j & 1);
            if (row < N_TOK && col < N_TOK)
                accS[nf][j] = accS[nf][j] * SCALE + bh[row * N_TOK + col];
            else
                accS[nf][j] = -1e30f;
        }
    }
    float mA = -1e30f, mB = -1e30f;
    #pragma unroll
    for (int nf = 0; nf < 8; ++nf) {
        mA = fmaxf(mA, fmaxf(accS[nf][0], accS[nf][1]));
        mB = fmaxf(mB, fmaxf(accS[nf][2], accS[nf][3]));
    }
    mA = fmaxf(mA, __shfl_xor_sync(0xFFFFFFFF, mA, 1));
    mA = fmaxf(mA, __shfl_xor_sync(0xFFFFFFFF, mA, 2));
    mB = fmaxf(mB, __shfl_xor_sync(0xFFFFFFFF, mB, 1));
    mB = fmaxf(mB, __shfl_xor_sync(0xFFFFFFFF, mB, 2));

    float sA = 0.0f, sB = 0.0f;
    #pragma unroll
    for (int nf = 0; nf < 8; ++nf) {
        #pragma unroll
        for (int j = 0; j < 4; ++j) {
            float m = (j < 2) ? mA : mB;
            float e = (accS[nf][j] > -1e29f) ? __expf(accS[nf][j] - m) : 0.0f;
            accS[nf][j] = e;
            if (j < 2) sA += e; else sB += e;
        }
    }
    sA += __shfl_xor_sync(0xFFFFFFFF, sA, 1);
    sA += __shfl_xor_sync(0xFFFFFFFF, sA, 2);
    sB += __shfl_xor_sync(0xFFFFFFFF, sB, 1);
    sB += __shfl_xor_sync(0xFFFFFFFF, sB, 2);
    const float invA = 1.0f / fmaxf(sA, 1e-30f);
    const float invB = 1.0f / fmaxf(sB, 1e-30f);
    #pragma unroll
    for (int nf = 0; nf < 8; ++nf) {
        accS[nf][0] *= invA; accS[nf][1] *= invA;
        accS[nf][2] *= invB; accS[nf][3] *= invB;
    }

    float accO[4][4];
    #pragma unroll
    for (int nf = 0; nf < 4; ++nf)
        #pragma unroll
        for (int r = 0; r < 4; ++r) accO[nf][r] = 0.0f;

    #pragma unroll
    for (int kt = 0; kt < 4; ++kt) {
        uint32_t aph[4], apl[4];
        #pragma unroll
        for (int q = 0; q < 4; ++q) {
            const int nf = 2 * kt + (q >> 1);
            const int j0 = (q & 1) * 2;
            float p0 = accS[nf][j0], p1 = accS[nf][j0 + 1];
            __nv_bfloat162 hi2 = __floats2bfloat162_rn(p0, p1);
            __nv_bfloat162 lo2 = __floats2bfloat162_rn(
                p0 - __bfloat162float(hi2.x), p1 - __bfloat162float(hi2.y));
            aph[q] = *(uint32_t*)&hi2;
            apl[q] = *(uint32_t*)&lo2;
        }
        const uint32_t koff = kt * 32 + khi;
        uint32_t bvh[4][2], bvl[4][2];
        #pragma unroll
        for (int g = 0; g < 2; ++g) {
            uint32_t off = (g * 16 + lrow) * (VT_STRIDE * 2) + koff;
            uint32_t r0, r1, r2, r3;
            LDSM_X4(r0, r1, r2, r3, vhb + off);
            bvh[2 * g][0] = r0; bvh[2 * g][1] = r2;
            bvh[2 * g + 1][0] = r1; bvh[2 * g + 1][1] = r3;
            LDSM_X4(r0, r1, r2, r3, vlb + off);
            bvl[2 * g][0] = r0; bvl[2 * g][1] = r2;
            bvl[2 * g + 1][0] = r1; bvl[2 * g + 1][1] = r3;
        }
        #pragma unroll
        for (int nf = 0; nf < 4; ++nf) {
            MMA_BF16(accO[nf], aph, bvh[nf]);
            MMA_BF16(accO[nf], aph, bvl[nf]);
            MMA_BF16(accO[nf], apl, bvh[nf]);
        }
    }

    // epilogue: fp16 hi/lo split of ctx
    #pragma unroll
    for (int half_i = 0; half_i < 2; ++half_i) {
        int row = (half_i == 0) ? rA : rB;
        if (row < N_TOK) {
            size_t obase = (size_t)(b * N_TOK + row) * DIM + h * HD;
            #pragma unroll
            for (int nf = 0; nf < 4; ++nf) {
                int d = nf * 8 + c0;
                float v0 = accO[nf][2 * half_i + 0];
                float v1 = accO[nf][2 * half_i + 1];
                __half2 hi2 = __floats2half2_rn(v0, v1);
                __half2 lo2 = __floats2half2_rn(
                    v0 - __half2float(hi2.x), v1 - __half2float(hi2.y));
                *(__half2*)(ctx_hi + obase + d) = hi2;
                *(__half2*)(ctx_lo + obase + d) = lo2;
            }
        }
    }
}

// ---------------------------------------------------------------------------
extern "C" void kernel_launch(void* const* d_in, const int* in_sizes, int n_in,
                              void* d_out, int out_size)
{
    const float* x      = (const float*)d_in[0];
    const float* qkv_w  = (const float*)d_in[1];
    const float* qkv_b  = (const float*)d_in[2];
    const float* proj_w = (const float*)d_in[3];
    const float* proj_b = (const float*)d_in[4];
    const float* rpb    = (const float*)d_in[5];
    const int*   ridx   = (const int*)d_in[6];
    float* out = (float*)d_out;

    __half *xh, *chi, *clo, *wqh, *wql, *wph, *wpl;
    float *qkv_s, *biasm;
    cudaGetSymbolAddress((void**)&xh,    g_xh);
    cudaGetSymbolAddress((void**)&qkv_s, g_qkv);
    cudaGetSymbolAddress((void**)&chi,   g_chi);
    cudaGetSymbolAddress((void**)&clo,   g_clo);
    cudaGetSymbolAddress((void**)&wqh,   g_wqh);
    cudaGetSymbolAddress((void**)&wql,   g_wql);
    cudaGetSymbolAddress((void**)&wph,   g_wph);
    cudaGetSymbolAddress((void**)&wpl,   g_wpl);
    cudaGetSymbolAddress((void**)&biasm, g_bias);

    const int smem2 = 2 * 3 * HALF_B;   // 61440
    const int smem3 = 2 * 4 * HALF_B;   // 81920
    static bool attr_set = false;
    if (!attr_set) {
        cudaFuncSetAttribute(gemm_f16<false>, cudaFuncAttributeMaxDynamicSharedMemorySize, smem2);
        cudaFuncSetAttribute(gemm_f16<true>,  cudaFuncAttributeMaxDynamicSharedMemorySize, smem3);
        attr_set = true;
    }

    // 0) bias table
    bias_kernel<<<HEADS, 256>>>(rpb, ridx, biasm);

    // 1) splits: x -> fp16 single; weights -> fp16 hi/lo
    {
        int n4 = (M_TOT * DIM) / 4;
        split_h1<<<(n4 + 255) / 256, 256>>>(x, xh, n4);
        int w4 = (QKV_N * DIM) / 4;
        split_h2<<<(w4 + 255) / 256, 256>>>(qkv_w, wqh, wql, w4);
        int p4 = (DIM * DIM) / 4;
        split_h2<<<(p4 + 255) / 256, 256>>>(proj_w, wph, wpl, p4);
    }

    // 2) QKV GEMM (2-term fp16) -> fp32 qkv
    {
        dim3 grid(QKV_N / 128, M_TOT / 128);   // (9, 1568)
        gemm_f16<false><<<grid, 256, smem2>>>(xh, nullptr, wqh, wql, qkv_b, qkv_s, QKV_N);
    }

    // 3) Attention (tensor-core, register softmax, fp16 hi/lo ctx)
    {
        dim3 grid(B_WIN, HEADS);
        attn_kernel<<<grid, 128>>>(qkv_s, biasm, chi, clo);
    }

    // 4) Projection GEMM (3-term fp16) -> fp32 out
    {
        dim3 grid(DIM / 128, M_TOT / 128);     // (3, 1568)
        gemm_f16<true><<<grid, 256, smem3>>>(chi, clo, wph, wpl, proj_b, out, DIM);
    }
}

// round 7
// speedup vs baseline: 2.8650x; 1.0381x over previous
#include <cuda_runtime.h>
#include <cuda_fp16.h>
#include <math.h>
#include <stdint.h>

// Problem constants
#define B_WIN 4096
#define N_TOK 49
#define DIM   384
#define HEADS 12
#define HD    32
#define M_TOT (B_WIN * N_TOK)     // 200704
#define QKV_N (3 * DIM)           // 1152
#define KTOT  384
#define SCALE 0.17677669529663687f

// ---------------------------------------------------------------------------
// Scratch (static device globals — allocation-guard safe)
// ---------------------------------------------------------------------------
__device__ __half  g_xh  [(size_t)M_TOT * DIM];
__device__ __half  g_qkvh[(size_t)M_TOT * QKV_N];   // q(scaled)|k|v_hi, fp16
__device__ __half  g_vlo [(size_t)M_TOT * DIM];     // v_lo fp16
__device__ __half  g_ctx [(size_t)M_TOT * DIM];     // attention output fp16
__device__ __half  g_wqh [(size_t)QKV_N * DIM];
__device__ __half  g_wql [(size_t)QKV_N * DIM];
__device__ __half  g_wph [(size_t)DIM * DIM];
__device__ __half  g_wpl [(size_t)DIM * DIM];
__device__ float   g_bias[HEADS * N_TOK * N_TOK];   // [12][49][49]

// ---------------------------------------------------------------------------
// PTX helpers (sm_80-compatible only)
// ---------------------------------------------------------------------------
__device__ __forceinline__ uint32_t smem_u32(const void* p) {
    uint32_t a;
    asm("{ .reg .u64 t; cvta.to.shared.u64 t, %1; cvt.u32.u64 %0, t; }" : "=r"(a) : "l"(p));
    return a;
}

#define CP_ASYNC16(dst, src) \
    asm volatile("cp.async.cg.shared.global [%0], [%1], 16;" :: "r"(dst), "l"(src))
#define CP_COMMIT() asm volatile("cp.async.commit_group;" ::: "memory")
#define CP_WAIT2()  asm volatile("cp.async.wait_group 2;" ::: "memory")

#define LDSM_X4(r0, r1, r2, r3, addr) \
    asm volatile("ldmatrix.sync.aligned.m8n8.x4.shared.b16 {%0,%1,%2,%3}, [%4];" \
        : "=r"(r0), "=r"(r1), "=r"(r2), "=r"(r3) : "r"(addr))

#define MMA_F16(d, a, b) \
    asm volatile("mma.sync.aligned.m16n8k16.row.col.f32.f16.f16.f32 " \
        "{%0,%1,%2,%3}, {%4,%5,%6,%7}, {%8,%9}, {%0,%1,%2,%3};" \
        : "+f"((d)[0]), "+f"((d)[1]), "+f"((d)[2]), "+f"((d)[3]) \
        : "r"((a)[0]), "r"((a)[1]), "r"((a)[2]), "r"((a)[3]), \
          "r"((b)[0]), "r"((b)[1]))

// ---------------------------------------------------------------------------
// Bias precompute: g_bias[h][ij] = rpb[ridx[ij]*12 + h]
// ---------------------------------------------------------------------------
__global__ void bias_kernel(const float* __restrict__ rpb, const int* __restrict__ ridx,
                            float* __restrict__ bias)
{
    int h = blockIdx.x;
    for (int ij = threadIdx.x; ij < N_TOK * N_TOK; ij += blockDim.x)
        bias[h * N_TOK * N_TOK + ij] = rpb[ridx[ij] * HEADS + h];
}

// ---------------------------------------------------------------------------
// Splits
// ---------------------------------------------------------------------------
__global__ void split_h1(const float* __restrict__ src, __half* __restrict__ dst, int n4)
{
    int i = blockIdx.x * blockDim.x + threadIdx.x;
    if (i >= n4) return;
    float4 v = ((const float4*)src)[i];
    __half2* D = (__half2*)dst;
    D[2 * i]     = __floats2half2_rn(v.x, v.y);
    D[2 * i + 1] = __floats2half2_rn(v.z, v.w);
}

__global__ void split_h2(const float* __restrict__ src,
                         __half* __restrict__ hi, __half* __restrict__ lo, int n4)
{
    int i = blockIdx.x * blockDim.x + threadIdx.x;
    if (i >= n4) return;
    float4 v = ((const float4*)src)[i];
    __half2 h0 = __floats2half2_rn(v.x, v.y);
    __half2 h1 = __floats2half2_rn(v.z, v.w);
    __half2 l0 = __floats2half2_rn(v.x - __half2float(h0.x), v.y - __half2float(h0.y));
    __half2 l1 = __floats2half2_rn(v.z - __half2float(h1.x), v.w - __half2float(h1.y));
    ((__half2*)hi)[2 * i] = h0; ((__half2*)hi)[2 * i + 1] = h1;
    ((__half2*)lo)[2 * i] = l0; ((__half2*)lo)[2 * i + 1] = l1;
}

// ---------------------------------------------------------------------------
// 2-term fp16 GEMM: C[M,N] = A[M,384] @ (Whi+Wlo)[N,384]^T + bias
// 128x128 tile, 256 thr, 3-stage cp.async, 2 CTAs/SM.
// EPI=0: fp32 out.  EPI=1: QKV epilogue (scale q cols, fp16 out + v_lo).
// ---------------------------------------------------------------------------
#define BK        32
#define NCHUNK    (KTOT / BK)            // 12
#define ASTRIDE   80                     // bytes per 32-half row (64 + 16 pad)
#define HALF_B    (128 * ASTRIDE)        // 10240
#define STAGE_B   (3 * HALF_B)           // 30720 (A | Bh | Bl)
#define GEMM_SMEM (3 * STAGE_B)          // 92160

template<int EPI>
__global__ void __launch_bounds__(256, 2) gemm_f16(
    const __half* __restrict__ Ah,
    const __half* __restrict__ Bh, const __half* __restrict__ Bl,
    const float* __restrict__ bias,
    float* __restrict__ Cf, __half* __restrict__ Ch, __half* __restrict__ Vlo,
    int N)
{
    extern __shared__ char smem[];
    const uint32_t sb = smem_u32(smem);
    const int tid  = threadIdx.x;
    const int lane = tid & 31;
    const int wid  = tid >> 5;
    const int warp_m = wid & 1;
    const int warp_n = wid >> 1;
    const int bm = blockIdx.y * 128;
    const int bn = blockIdx.x * 128;

    float acc[4][4][4];
    #pragma unroll
    for (int i = 0; i < 4; ++i)
        #pragma unroll
        for (int j = 0; j < 4; ++j)
            #pragma unroll
            for (int r = 0; r < 4; ++r) acc[i][j][r] = 0.0f;

    const __half* srcs[3] = {Ah, Bh, Bl};

    auto load_chunk = [&](int stage, int kc) {
        #pragma unroll
        for (int t = 0; t < 3; ++t) {
            const __half* src = srcs[t];
            const int rbase = (t == 0) ? bm : bn;
            const uint32_t hoff = sb + (uint32_t)stage * STAGE_B + (uint32_t)t * HALF_B;
            #pragma unroll
            for (int it = 0; it < 2; ++it) {
                int idx = tid + it * 256;
                int row = idx >> 2;
                int c16 = idx & 3;
                const __half* g = src + (size_t)(rbase + row) * KTOT + kc + c16 * 8;
                uint32_t dst = hoff + (uint32_t)(row * ASTRIDE + c16 * 16);
                CP_ASYNC16(dst, g);
            }
        }
    };

    load_chunk(0, 0);      CP_COMMIT();
    load_chunk(1, BK);     CP_COMMIT();
    load_chunk(2, 2 * BK); CP_COMMIT();

    for (int c = 0; c < NCHUNK; ++c) {
        CP_WAIT2();
        __syncthreads();

        const uint32_t base = sb + (uint32_t)(c % 3) * STAGE_B;
        #pragma unroll
        for (int ks = 0; ks < 2; ++ks) {
            const uint32_t koff = (uint32_t)(ks * 32) + ((lane >> 4) << 4);
            const uint32_t arow = (uint32_t)(warp_m * 64 + (lane & 15));
            const uint32_t brow = (uint32_t)(warp_n * 32 + (lane & 15));

            uint32_t ah[4][4], bh[4][2], bl[4][2];
            #pragma unroll
            for (int mf = 0; mf < 4; ++mf) {
                uint32_t a = base + (arow + mf * 16) * ASTRIDE + koff;
                LDSM_X4(ah[mf][0], ah[mf][1], ah[mf][2], ah[mf][3], a);
            }
            #pragma unroll
            for (int g = 0; g < 2; ++g) {
                uint32_t a = base + HALF_B + (brow + g * 16) * ASTRIDE + koff;
                uint32_t r0, r1, r2, r3;
                LDSM_X4(r0, r1, r2, r3, a);
                bh[2 * g][0] = r0; bh[2 * g][1] = r2;
                bh[2 * g + 1][0] = r1; bh[2 * g + 1][1] = r3;
                LDSM_X4(r0, r1, r2, r3, a + HALF_B);
                bl[2 * g][0] = r0; bl[2 * g][1] = r2;
                bl[2 * g + 1][0] = r1; bl[2 * g + 1][1] = r3;
            }
            #pragma unroll
            for (int mf = 0; mf < 4; ++mf)
                #pragma unroll
                for (int nf = 0; nf < 4; ++nf) {
                    MMA_F16(acc[mf][nf], ah[mf], bh[nf]);
                    MMA_F16(acc[mf][nf], ah[mf], bl[nf]);
                }
        }
        __syncthreads();
        if (c + 3 < NCHUNK) load_chunk(c % 3, (c + 3) * BK);
        CP_COMMIT();
    }

    // epilogue
    #pragma unroll
    for (int mf = 0; mf < 4; ++mf) {
        int row = bm + warp_m * 64 + mf * 16 + (lane >> 2);
        #pragma unroll
        for (int nf = 0; nf < 4; ++nf) {
            int col = bn + warp_n * 32 + nf * 8 + (lane & 3) * 2;
            float b0 = bias[col], b1 = bias[col + 1];
            #pragma unroll
            for (int hf = 0; hf < 2; ++hf) {
                int r = row + hf * 8;
                float v0 = acc[mf][nf][2 * hf + 0] + b0;
                float v1 = acc[mf][nf][2 * hf + 1] + b1;
                if (EPI == 0) {
                    *(float2*)(Cf + (size_t)r * N + col) = make_float2(v0, v1);
                } else {
                    // QKV: q cols [0,384) scaled; v cols [768,1152) get lo split
                    if (col < DIM) { v0 *= SCALE; v1 *= SCALE; }
                    __half2 h2 = __floats2half2_rn(v0, v1);
                    *(__half2*)(Ch + (size_t)r * N + col) = h2;
                    if (col >= 2 * DIM) {
                        __half2 l2 = __floats2half2_rn(
                            v0 - __half2float(h2.x), v1 - __half2float(h2.y));
                        *(__half2*)(Vlo + (size_t)r * DIM + (col - 2 * DIM)) = l2;
                    }
                }
            }
        }
    }
}

// ---------------------------------------------------------------------------
// Tensorized attention, register-resident softmax.
// qkv fp16 (q pre-scaled), v fp16 hi/lo. ctx written as single fp16.
// One CTA per (window b, head h), 128 threads (4 warps).
// ---------------------------------------------------------------------------
#define QK_STRIDE 40      // halves per row (32 data + 8 pad) = 80B
#define VT_STRIDE 72      // halves per row (64 data + 8 pad) = 144B

__global__ void __launch_bounds__(128) attn_kernel(
    const __half* __restrict__ qkv, const __half* __restrict__ vlo,
    const float* __restrict__ bias_mat,
    __half* __restrict__ ctx)
{
    const int b = blockIdx.x;
    const int h = blockIdx.y;
    const int tid = threadIdx.x;
    const int lane = tid & 31;
    const int w = tid >> 5;

    __shared__ __half qs [64 * QK_STRIDE];
    __shared__ __half kss[64 * QK_STRIDE];
    __shared__ __half vth[32 * VT_STRIDE];
    __shared__ __half vtl[32 * VT_STRIDE];

    for (int i = tid; i < 64 * QK_STRIDE / 2; i += 128) {
        ((uint32_t*)qs)[i]  = 0;
        ((uint32_t*)kss)[i] = 0;
    }
    for (int i = tid; i < 32 * VT_STRIDE / 2; i += 128) {
        ((uint32_t*)vth)[i] = 0;
        ((uint32_t*)vtl)[i] = 0;
    }
    __syncthreads();

    // 16 chunks of 8 halves per token: q(4) k(4) vhi(4) vlo(4)
    for (int idx = tid; idx < N_TOK * 16; idx += 128) {
        int n  = idx >> 4;
        int r  = idx & 15;
        int t  = r >> 2;
        int c8 = (r & 3) * 8;
        size_t rowb = (size_t)(b * N_TOK + n);
        if (t < 2) {
            const __half* src = qkv + rowb * QKV_N + h * HD + t * DIM + c8;
            *(uint4*)((t == 0 ? qs : kss) + n * QK_STRIDE + c8) = *(const uint4*)src;
        } else {
            const __half* src = (t == 2)
                ? qkv + rowb * QKV_N + h * HD + 2 * DIM + c8
                : vlo + rowb * DIM + h * HD + c8;
            __half tmp[8];
            *(uint4*)tmp = *(const uint4*)src;
            __half* dst = (t == 2) ? vth : vtl;
            #pragma unroll
            for (int e = 0; e < 8; ++e)
                dst[(c8 + e) * VT_STRIDE + n] = tmp[e];
        }
    }
    __syncthreads();

    const uint32_t qb  = smem_u32(qs);
    const uint32_t kb  = smem_u32(kss);
    const uint32_t vhb = smem_u32(vth);
    const uint32_t vlb = smem_u32(vtl);
    const int lrow = lane & 15;
    const int khi  = (lane >> 4) * 16;

    // ---- S = Q @ K^T ----
    float accS[8][4];
    #pragma unroll
    for (int nf = 0; nf < 8; ++nf)
        #pragma unroll
        for (int r = 0; r < 4; ++r) accS[nf][r] = 0.0f;

    #pragma unroll
    for (int ki = 0; ki < 2; ++ki) {
        const uint32_t koff = ki * 32 + khi;
        uint32_t a[4];
        LDSM_X4(a[0], a[1], a[2], a[3], qb + (w * 16 + lrow) * (QK_STRIDE * 2) + koff);
        uint32_t bfr[8][2];
        #pragma unroll
        for (int g = 0; g < 4; ++g) {
            uint32_t r0, r1, r2, r3;
            LDSM_X4(r0, r1, r2, r3, kb + (g * 16 + lrow) * (QK_STRIDE * 2) + koff);
            bfr[2 * g][0] = r0; bfr[2 * g][1] = r2;
            bfr[2 * g + 1][0] = r1; bfr[2 * g + 1][1] = r3;
        }
        #pragma unroll
        for (int nf = 0; nf < 8; ++nf) MMA_F16(accS[nf], a, bfr[nf]);
    }

    // ---- register softmax (q pre-scaled, so just + bias) ----
    const int rA = w * 16 + (lane >> 2);
    const int rB = rA + 8;
    const int c0 = (lane & 3) * 2;
    const float* bh = bias_mat + h * N_TOK * N_TOK;

    #pragma unroll
    for (int nf = 0; nf < 8; ++nf) {
        #pragma unroll
        for (int j = 0; j < 4; ++j) {
            int row = (j < 2) ? rA : rB;
            int col = nf * 8 + c0 + (j & 1);
            if (row < N_TOK && col < N_TOK)
                accS[nf][j] = accS[nf][j] + bh[row * N_TOK + col];
            else
                accS[nf][j] = -1e30f;
        }
    }
    float mA = -1e30f, mB = -1e30f;
    #pragma unroll
    for (int nf = 0; nf < 8; ++nf) {
        mA = fmaxf(mA, fmaxf(accS[nf][0], accS[nf][1]));
        mB = fmaxf(mB, fmaxf(accS[nf][2], accS[nf][3]));
    }
    mA = fmaxf(mA, __shfl_xor_sync(0xFFFFFFFF, mA, 1));
    mA = fmaxf(mA, __shfl_xor_sync(0xFFFFFFFF, mA, 2));
    mB = fmaxf(mB, __shfl_xor_sync(0xFFFFFFFF, mB, 1));
    mB = fmaxf(mB, __shfl_xor_sync(0xFFFFFFFF, mB, 2));

    float sA = 0.0f, sB = 0.0f;
    #pragma unroll
    for (int nf = 0; nf < 8; ++nf) {
        #pragma unroll
        for (int j = 0; j < 4; ++j) {
            float m = (j < 2) ? mA : mB;
            float e = (accS[nf][j] > -1e29f) ? __expf(accS[nf][j] - m) : 0.0f;
            accS[nf][j] = e;
            if (j < 2) sA += e; else sB += e;
        }
    }
    sA += __shfl_xor_sync(0xFFFFFFFF, sA, 1);
    sA += __shfl_xor_sync(0xFFFFFFFF, sA, 2);
    sB += __shfl_xor_sync(0xFFFFFFFF, sB, 1);
    sB += __shfl_xor_sync(0xFFFFFFFF, sB, 2);
    const float invA = 1.0f / fmaxf(sA, 1e-30f);
    const float invB = 1.0f / fmaxf(sB, 1e-30f);
    #pragma unroll
    for (int nf = 0; nf < 8; ++nf) {
        accS[nf][0] *= invA; accS[nf][1] *= invA;
        accS[nf][2] *= invB; accS[nf][3] *= invB;
    }

    // ---- out = P @ V (fp16 hi/lo, 3 terms) ----
    float accO[4][4];
    #pragma unroll
    for (int nf = 0; nf < 4; ++nf)
        #pragma unroll
        for (int r = 0; r < 4; ++r) accO[nf][r] = 0.0f;

    #pragma unroll
    for (int kt = 0; kt < 4; ++kt) {
        uint32_t aph[4], apl[4];
        #pragma unroll
        for (int q = 0; q < 4; ++q) {
            const int nf = 2 * kt + (q >> 1);
            const int j0 = (q & 1) * 2;
            float p0 = accS[nf][j0], p1 = accS[nf][j0 + 1];
            __half2 hi2 = __floats2half2_rn(p0, p1);
            __half2 lo2 = __floats2half2_rn(
                p0 - __half2float(hi2.x), p1 - __half2float(hi2.y));
            aph[q] = *(uint32_t*)&hi2;
            apl[q] = *(uint32_t*)&lo2;
        }
        const uint32_t koff = kt * 32 + khi;
        uint32_t bvh[4][2], bvl[4][2];
        #pragma unroll
        for (int g = 0; g < 2; ++g) {
            uint32_t off = (g * 16 + lrow) * (VT_STRIDE * 2) + koff;
            uint32_t r0, r1, r2, r3;
            LDSM_X4(r0, r1, r2, r3, vhb + off);
            bvh[2 * g][0] = r0; bvh[2 * g][1] = r2;
            bvh[2 * g + 1][0] = r1; bvh[2 * g + 1][1] = r3;
            LDSM_X4(r0, r1, r2, r3, vlb + off);
            bvl[2 * g][0] = r0; bvl[2 * g][1] = r2;
            bvl[2 * g + 1][0] = r1; bvl[2 * g + 1][1] = r3;
        }
        #pragma unroll
        for (int nf = 0; nf < 4; ++nf) {
            MMA_F16(accO[nf], aph, bvh[nf]);
            MMA_F16(accO[nf], aph, bvl[nf]);
            MMA_F16(accO[nf], apl, bvh[nf]);
        }
    }

    // epilogue: single fp16 ctx
    #pragma unroll
    for (int half_i = 0; half_i < 2; ++half_i) {
        int row = (half_i == 0) ? rA : rB;
        if (row < N_TOK) {
            size_t obase = (size_t)(b * N_TOK + row) * DIM + h * HD;
            #pragma unroll
            for (int nf = 0; nf < 4; ++nf) {
                int d = nf * 8 + c0;
                *(__half2*)(ctx + obase + d) = __floats2half2_rn(
                    accO[nf][2 * half_i + 0], accO[nf][2 * half_i + 1]);
            }
        }
    }
}

// ---------------------------------------------------------------------------
extern "C" void kernel_launch(void* const* d_in, const int* in_sizes, int n_in,
                              void* d_out, int out_size)
{
    const float* x      = (const float*)d_in[0];
    const float* qkv_w  = (const float*)d_in[1];
    const float* qkv_b  = (const float*)d_in[2];
    const float* proj_w = (const float*)d_in[3];
    const float* proj_b = (const float*)d_in[4];
    const float* rpb    = (const float*)d_in[5];
    const int*   ridx   = (const int*)d_in[6];
    float* out = (float*)d_out;

    __half *xh, *qkvh, *vlo, *ctx, *wqh, *wql, *wph, *wpl;
    float *biasm;
    cudaGetSymbolAddress((void**)&xh,    g_xh);
    cudaGetSymbolAddress((void**)&qkvh,  g_qkvh);
    cudaGetSymbolAddress((void**)&vlo,   g_vlo);
    cudaGetSymbolAddress((void**)&ctx,   g_ctx);
    cudaGetSymbolAddress((void**)&wqh,   g_wqh);
    cudaGetSymbolAddress((void**)&wql,   g_wql);
    cudaGetSymbolAddress((void**)&wph,   g_wph);
    cudaGetSymbolAddress((void**)&wpl,   g_wpl);
    cudaGetSymbolAddress((void**)&biasm, g_bias);

    static bool attr_set = false;
    if (!attr_set) {
        cudaFuncSetAttribute(gemm_f16<0>, cudaFuncAttributeMaxDynamicSharedMemorySize, GEMM_SMEM);
        cudaFuncSetAttribute(gemm_f16<1>, cudaFuncAttributeMaxDynamicSharedMemorySize, GEMM_SMEM);
        attr_set = true;
    }

    // 0) bias table
    bias_kernel<<<HEADS, 256>>>(rpb, ridx, biasm);

    // 1) splits
    {
        int n4 = (M_TOT * DIM) / 4;
        split_h1<<<(n4 + 255) / 256, 256>>>(x, xh, n4);
        int w4 = (QKV_N * DIM) / 4;
        split_h2<<<(w4 + 255) / 256, 256>>>(qkv_w, wqh, wql, w4);
        int p4 = (DIM * DIM) / 4;
        split_h2<<<(p4 + 255) / 256, 256>>>(proj_w, wph, wpl, p4);
    }

    // 2) QKV GEMM (2-term) -> fp16 qkv (+ v_lo)
    {
        dim3 grid(QKV_N / 128, M_TOT / 128);   // (9, 1568)
        gemm_f16<1><<<grid, 256, GEMM_SMEM>>>(xh, wqh, wql, qkv_b, nullptr, qkvh, vlo, QKV_N);
    }

    // 3) Attention
    {
        dim3 grid(B_WIN, HEADS);
        attn_kernel<<<grid, 128>>>(qkvh, vlo, biasm, ctx);
    }

    // 4) Projection GEMM (2-term) -> fp32 out
    {
        dim3 grid(DIM / 128, M_TOT / 128);     // (3, 1568)
        gemm_f16<0><<<grid, 256, GEMM_SMEM>>>(ctx, wph, wpl, proj_b, out, nullptr, nullptr, DIM);
    }
}

// round 8
// speedup vs baseline: 4.0501x; 1.4136x over previous
#include <cuda_runtime.h>
#include <cuda_fp16.h>
#include <math.h>
#include <stdint.h>

// Problem constants
#define B_WIN 4096
#define N_TOK 49
#define DIM   384
#define HEADS 12
#define HD    32
#define M_TOT (B_WIN * N_TOK)     // 200704
#define QKV_N (3 * DIM)           // 1152
#define KTOT  384
#define SCALE 0.17677669529663687f

// ---------------------------------------------------------------------------
// Scratch (static device globals — allocation-guard safe)
// ---------------------------------------------------------------------------
__device__ __half  g_xh  [(size_t)M_TOT * DIM];
__device__ __half  g_qkvh[(size_t)M_TOT * QKV_N];   // q(scaled)|k|v_hi, fp16
__device__ __half  g_vlo [(size_t)M_TOT * DIM];     // v_lo fp16
__device__ __half  g_ctx [(size_t)M_TOT * DIM];     // attention output fp16
__device__ __half  g_wqh [(size_t)QKV_N * DIM];
__device__ __half  g_wph [(size_t)DIM * DIM];
__device__ float   g_bias[HEADS * N_TOK * N_TOK];   // [12][49][49]

// ---------------------------------------------------------------------------
// PTX helpers (sm_80-compatible only)
// ---------------------------------------------------------------------------
__device__ __forceinline__ uint32_t smem_u32(const void* p) {
    uint32_t a;
    asm("{ .reg .u64 t; cvta.to.shared.u64 t, %1; cvt.u32.u64 %0, t; }" : "=r"(a) : "l"(p));
    return a;
}

#define CP_ASYNC16(dst, src) \
    asm volatile("cp.async.cg.shared.global [%0], [%1], 16;" :: "r"(dst), "l"(src))
#define CP_COMMIT() asm volatile("cp.async.commit_group;" ::: "memory")
#define CP_WAIT2()  asm volatile("cp.async.wait_group 2;" ::: "memory")

#define LDSM_X4(r0, r1, r2, r3, addr) \
    asm volatile("ldmatrix.sync.aligned.m8n8.x4.shared.b16 {%0,%1,%2,%3}, [%4];" \
        : "=r"(r0), "=r"(r1), "=r"(r2), "=r"(r3) : "r"(addr))

#define MMA_F16(d, a, b) \
    asm volatile("mma.sync.aligned.m16n8k16.row.col.f32.f16.f16.f32 " \
        "{%0,%1,%2,%3}, {%4,%5,%6,%7}, {%8,%9}, {%0,%1,%2,%3};" \
        : "+f"((d)[0]), "+f"((d)[1]), "+f"((d)[2]), "+f"((d)[3]) \
        : "r"((a)[0]), "r"((a)[1]), "r"((a)[2]), "r"((a)[3]), \
          "r"((b)[0]), "r"((b)[1]))

// ---------------------------------------------------------------------------
// Bias precompute
// ---------------------------------------------------------------------------
__global__ void bias_kernel(const float* __restrict__ rpb, const int* __restrict__ ridx,
                            float* __restrict__ bias)
{
    int h = blockIdx.x;
    for (int ij = threadIdx.x; ij < N_TOK * N_TOK; ij += blockDim.x)
        bias[h * N_TOK * N_TOK + ij] = rpb[ridx[ij] * HEADS + h];
}

// ---------------------------------------------------------------------------
// Split: fp32 -> fp16
// ---------------------------------------------------------------------------
__global__ void split_h1(const float* __restrict__ src, __half* __restrict__ dst, int n4)
{
    int i = blockIdx.x * blockDim.x + threadIdx.x;
    if (i >= n4) return;
    float4 v = ((const float4*)src)[i];
    __half2* D = (__half2*)dst;
    D[2 * i]     = __floats2half2_rn(v.x, v.y);
    D[2 * i + 1] = __floats2half2_rn(v.z, v.w);
}

// ---------------------------------------------------------------------------
// Single-term fp16 GEMM: C[M,N] = A[M,384] @ W[N,384]^T + bias
// 128x128 tile, 256 thr, 4-stage cp.async, 2 CTAs/SM.
// EPI=0: fp32 out.  EPI=1: QKV epilogue (scale q cols, fp16 out + v_lo).
// ---------------------------------------------------------------------------
#define BK        32
#define NCHUNK    (KTOT / BK)            // 12
#define NSTAGE    4
#define ASTRIDE   80                     // bytes per 32-half row (64 + 16 pad)
#define HALF_B    (128 * ASTRIDE)        // 10240
#define STAGE_B   (2 * HALF_B)           // 20480 (A | B)
#define GEMM_SMEM (NSTAGE * STAGE_B)     // 81920

template<int EPI>
__global__ void __launch_bounds__(256, 2) gemm_f16(
    const __half* __restrict__ Ah, const __half* __restrict__ Bh,
    const float* __restrict__ bias,
    float* __restrict__ Cf, __half* __restrict__ Ch, __half* __restrict__ Vlo,
    int N)
{
    extern __shared__ char smem[];
    const uint32_t sb = smem_u32(smem);
    const int tid  = threadIdx.x;
    const int lane = tid & 31;
    const int wid  = tid >> 5;
    const int warp_m = wid & 1;
    const int warp_n = wid >> 1;
    const int bm = blockIdx.y * 128;
    const int bn = blockIdx.x * 128;

    float acc[4][4][4];
    #pragma unroll
    for (int i = 0; i < 4; ++i)
        #pragma unroll
        for (int j = 0; j < 4; ++j)
            #pragma unroll
            for (int r = 0; r < 4; ++r) acc[i][j][r] = 0.0f;

    auto load_chunk = [&](int stage, int kc) {
        #pragma unroll
        for (int t = 0; t < 2; ++t) {
            const __half* src = (t == 0) ? Ah : Bh;
            const int rbase = (t == 0) ? bm : bn;
            const uint32_t hoff = sb + (uint32_t)stage * STAGE_B + (uint32_t)t * HALF_B;
            #pragma unroll
            for (int it = 0; it < 2; ++it) {
                int idx = tid + it * 256;
                int row = idx >> 2;
                int c16 = idx & 3;
                const __half* g = src + (size_t)(rbase + row) * KTOT + kc + c16 * 8;
                uint32_t dst = hoff + (uint32_t)(row * ASTRIDE + c16 * 16);
                CP_ASYNC16(dst, g);
            }
        }
    };

    load_chunk(0, 0);      CP_COMMIT();
    load_chunk(1, BK);     CP_COMMIT();
    load_chunk(2, 2 * BK); CP_COMMIT();

    for (int c = 0; c < NCHUNK; ++c) {
        CP_WAIT2();
        __syncthreads();

        // prefetch chunk c+3 into the stage freed last iteration
        if (c + 3 < NCHUNK) load_chunk((c + 3) % NSTAGE, (c + 3) * BK);
        CP_COMMIT();

        const uint32_t base = sb + (uint32_t)(c % NSTAGE) * STAGE_B;
        #pragma unroll
        for (int ks = 0; ks < 2; ++ks) {
            const uint32_t koff = (uint32_t)(ks * 32) + ((lane >> 4) << 4);
            const uint32_t arow = (uint32_t)(warp_m * 64 + (lane & 15));
            const uint32_t brow = (uint32_t)(warp_n * 32 + (lane & 15));

            uint32_t ah[4][4], bh[4][2];
            #pragma unroll
            for (int mf = 0; mf < 4; ++mf) {
                uint32_t a = base + (arow + mf * 16) * ASTRIDE + koff;
                LDSM_X4(ah[mf][0], ah[mf][1], ah[mf][2], ah[mf][3], a);
            }
            #pragma unroll
            for (int g = 0; g < 2; ++g) {
                uint32_t a = base + HALF_B + (brow + g * 16) * ASTRIDE + koff;
                uint32_t r0, r1, r2, r3;
                LDSM_X4(r0, r1, r2, r3, a);
                bh[2 * g][0] = r0; bh[2 * g][1] = r2;
                bh[2 * g + 1][0] = r1; bh[2 * g + 1][1] = r3;
            }
            #pragma unroll
            for (int mf = 0; mf < 4; ++mf)
                #pragma unroll
                for (int nf = 0; nf < 4; ++nf)
                    MMA_F16(acc[mf][nf], ah[mf], bh[nf]);
        }
    }

    // epilogue
    #pragma unroll
    for (int mf = 0; mf < 4; ++mf) {
        int row = bm + warp_m * 64 + mf * 16 + (lane >> 2);
        #pragma unroll
        for (int nf = 0; nf < 4; ++nf) {
            int col = bn + warp_n * 32 + nf * 8 + (lane & 3) * 2;
            float b0 = bias[col], b1 = bias[col + 1];
            #pragma unroll
            for (int hf = 0; hf < 2; ++hf) {
                int r = row + hf * 8;
                float v0 = acc[mf][nf][2 * hf + 0] + b0;
                float v1 = acc[mf][nf][2 * hf + 1] + b1;
                if (EPI == 0) {
                    *(float2*)(Cf + (size_t)r * N + col) = make_float2(v0, v1);
                } else {
                    if (col < DIM) { v0 *= SCALE; v1 *= SCALE; }
                    __half2 h2 = __floats2half2_rn(v0, v1);
                    *(__half2*)(Ch + (size_t)r * N + col) = h2;
                    if (col >= 2 * DIM) {
                        __half2 l2 = __floats2half2_rn(
                            v0 - __half2float(h2.x), v1 - __half2float(h2.y));
                        *(__half2*)(Vlo + (size_t)r * DIM + (col - 2 * DIM)) = l2;
                    }
                }
            }
        }
    }
}

// ---------------------------------------------------------------------------
// Tensorized attention, register-resident softmax (validated R5-R7).
// qkv fp16 (q pre-scaled), v fp16 hi/lo. ctx single fp16.
// ---------------------------------------------------------------------------
#define QK_STRIDE 40      // halves per row (32 data + 8 pad) = 80B
#define VT_STRIDE 72      // halves per row (64 data + 8 pad) = 144B

__global__ void __launch_bounds__(128) attn_kernel(
    const __half* __restrict__ qkv, const __half* __restrict__ vlo,
    const float* __restrict__ bias_mat,
    __half* __restrict__ ctx)
{
    const int b = blockIdx.x;
    const int h = blockIdx.y;
    const int tid = threadIdx.x;
    const int lane = tid & 31;
    const int w = tid >> 5;

    __shared__ __half qs [64 * QK_STRIDE];
    __shared__ __half kss[64 * QK_STRIDE];
    __shared__ __half vth[32 * VT_STRIDE];
    __shared__ __half vtl[32 * VT_STRIDE];

    // zero only what ldmatrix can read but loads don't write:
    // qs/kss rows 49..63 (u32 idx [980, 1280)); vth/vtl halves [48,64) per row
    for (int i = tid; i < 300; i += 128) {
        ((uint32_t*)qs)[980 + i]  = 0;
        ((uint32_t*)kss)[980 + i] = 0;
    }
    for (int i = tid; i < 256; i += 128) {
        int r = i >> 3, j = i & 7;
        ((uint32_t*)vth)[r * 36 + 24 + j] = 0;
        ((uint32_t*)vtl)[r * 36 + 24 + j] = 0;
    }
    __syncthreads();

    // 16 chunks of 8 halves per token: q(4) k(4) vhi(4) vlo(4)
    for (int idx = tid; idx < N_TOK * 16; idx += 128) {
        int n  = idx >> 4;
        int r  = idx & 15;
        int t  = r >> 2;
        int c8 = (r & 3) * 8;
        size_t rowb = (size_t)(b * N_TOK + n);
        if (t < 2) {
            const __half* src = qkv + rowb * QKV_N + h * HD + t * DIM + c8;
            *(uint4*)((t == 0 ? qs : kss) + n * QK_STRIDE + c8) = *(const uint4*)src;
        } else {
            const __half* src = (t == 2)
                ? qkv + rowb * QKV_N + h * HD + 2 * DIM + c8
                : vlo + rowb * DIM + h * HD + c8;
            __half tmp[8];
            *(uint4*)tmp = *(const uint4*)src;
            __half* dst = (t == 2) ? vth : vtl;
            #pragma unroll
            for (int e = 0; e < 8; ++e)
                dst[(c8 + e) * VT_STRIDE + n] = tmp[e];
        }
    }
    __syncthreads();

    const uint32_t qb  = smem_u32(qs);
    const uint32_t kb  = smem_u32(kss);
    const uint32_t vhb = smem_u32(vth);
    const uint32_t vlb = smem_u32(vtl);
    const int lrow = lane & 15;
    const int khi  = (lane >> 4) * 16;

    // ---- S = Q @ K^T ----
    float accS[8][4];
    #pragma unroll
    for (int nf = 0; nf < 8; ++nf)
        #pragma unroll
        for (int r = 0; r < 4; ++r) accS[nf][r] = 0.0f;

    #pragma unroll
    for (int ki = 0; ki < 2; ++ki) {
        const uint32_t koff = ki * 32 + khi;
        uint32_t a[4];
        LDSM_X4(a[0], a[1], a[2], a[3], qb + (w * 16 + lrow) * (QK_STRIDE * 2) + koff);
        uint32_t bfr[8][2];
        #pragma unroll
        for (int g = 0; g < 4; ++g) {
            uint32_t r0, r1, r2, r3;
            LDSM_X4(r0, r1, r2, r3, kb + (g * 16 + lrow) * (QK_STRIDE * 2) + koff);
            bfr[2 * g][0] = r0; bfr[2 * g][1] = r2;
            bfr[2 * g + 1][0] = r1; bfr[2 * g + 1][1] = r3;
        }
        #pragma unroll
        for (int nf = 0; nf < 8; ++nf) MMA_F16(accS[nf], a, bfr[nf]);
    }

    // ---- register softmax (q pre-scaled; just + bias) ----
    const int rA = w * 16 + (lane >> 2);
    const int rB = rA + 8;
    const int c0 = (lane & 3) * 2;
    const float* bh = bias_mat + h * N_TOK * N_TOK;

    #pragma unroll
    for (int nf = 0; nf < 8; ++nf) {
        #pragma unroll
        for (int j = 0; j < 4; ++j) {
            int row = (j < 2) ? rA : rB;
            int col = nf * 8 + c0 + (j & 1);
            if (row < N_TOK && col < N_TOK)
                accS[nf][j] = accS[nf][j] + bh[row * N_TOK + col];
            else
                accS[nf][j] = -1e30f;
        }
    }
    float mA = -1e30f, mB = -1e30f;
    #pragma unroll
    for (int nf = 0; nf < 8; ++nf) {
        mA = fmaxf(mA, fmaxf(accS[nf][0], accS[nf][1]));
        mB = fmaxf(mB, fmaxf(accS[nf][2], accS[nf][3]));
    }
    mA = fmaxf(mA, __shfl_xor_sync(0xFFFFFFFF, mA, 1));
    mA = fmaxf(mA, __shfl_xor_sync(0xFFFFFFFF, mA, 2));
    mB = fmaxf(mB, __shfl_xor_sync(0xFFFFFFFF, mB, 1));
    mB = fmaxf(mB, __shfl_xor_sync(0xFFFFFFFF, mB, 2));

    float sA = 0.0f, sB = 0.0f;
    #pragma unroll
    for (int nf = 0; nf < 8; ++nf) {
        #pragma unroll
        for (int j = 0; j < 4; ++j) {
            float m = (j < 2) ? mA : mB;
            float e = (accS[nf][j] > -1e29f) ? __expf(accS[nf][j] - m) : 0.0f;
            accS[nf][j] = e;
            if (j < 2) sA += e; else sB += e;
        }
    }
    sA += __shfl_xor_sync(0xFFFFFFFF, sA, 1);
    sA += __shfl_xor_sync(0xFFFFFFFF, sA, 2);
    sB += __shfl_xor_sync(0xFFFFFFFF, sB, 1);
    sB += __shfl_xor_sync(0xFFFFFFFF, sB, 2);
    const float invA = 1.0f / fmaxf(sA, 1e-30f);
    const float invB = 1.0f / fmaxf(sB, 1e-30f);
    #pragma unroll
    for (int nf = 0; nf < 8; ++nf) {
        accS[nf][0] *= invA; accS[nf][1] *= invA;
        accS[nf][2] *= invB; accS[nf][3] *= invB;
    }

    // ---- out = P @ V (fp16 hi/lo, 3 terms) ----
    float accO[4][4];
    #pragma unroll
    for (int nf = 0; nf < 4; ++nf)
        #pragma unroll
        for (int r = 0; r < 4; ++r) accO[nf][r] = 0.0f;

    #pragma unroll
    for (int kt = 0; kt < 4; ++kt) {
        uint32_t aph[4], apl[4];
        #pragma unroll
        for (int q = 0; q < 4; ++q) {
            const int nf = 2 * kt + (q >> 1);
            const int j0 = (q & 1) * 2;
            float p0 = accS[nf][j0], p1 = accS[nf][j0 + 1];
            __half2 hi2 = __floats2half2_rn(p0, p1);
            __half2 lo2 = __floats2half2_rn(
                p0 - __half2float(hi2.x), p1 - __half2float(hi2.y));
            aph[q] = *(uint32_t*)&hi2;
            apl[q] = *(uint32_t*)&lo2;
        }
        const uint32_t koff = kt * 32 + khi;
        uint32_t bvh[4][2], bvl[4][2];
        #pragma unroll
        for (int g = 0; g < 2; ++g) {
            uint32_t off = (g * 16 + lrow) * (VT_STRIDE * 2) + koff;
            uint32_t r0, r1, r2, r3;
            LDSM_X4(r0, r1, r2, r3, vhb + off);
            bvh[2 * g][0] = r0; bvh[2 * g][1] = r2;
            bvh[2 * g + 1][0] = r1; bvh[2 * g + 1][1] = r3;
            LDSM_X4(r0, r1, r2, r3, vlb + off);
            bvl[2 * g][0] = r0; bvl[2 * g][1] = r2;
            bvl[2 * g + 1][0] = r1; bvl[2 * g + 1][1] = r3;
        }
        #pragma unroll
        for (int nf = 0; nf < 4; ++nf) {
            MMA_F16(accO[nf], aph, bvh[nf]);
            MMA_F16(accO[nf], aph, bvl[nf]);
            MMA_F16(accO[nf], apl, bvh[nf]);
        }
    }

    // epilogue: single fp16 ctx
    #pragma unroll
    for (int half_i = 0; half_i < 2; ++half_i) {
        int row = (half_i == 0) ? rA : rB;
        if (row < N_TOK) {
            size_t obase = (size_t)(b * N_TOK + row) * DIM + h * HD;
            #pragma unroll
            for (int nf = 0; nf < 4; ++nf) {
                int d = nf * 8 + c0;
                *(__half2*)(ctx + obase + d) = __floats2half2_rn(
                    accO[nf][2 * half_i + 0], accO[nf][2 * half_i + 1]);
            }
        }
    }
}

// ---------------------------------------------------------------------------
extern "C" void kernel_launch(void* const* d_in, const int* in_sizes, int n_in,
                              void* d_out, int out_size)
{
    const float* x      = (const float*)d_in[0];
    const float* qkv_w  = (const float*)d_in[1];
    const float* qkv_b  = (const float*)d_in[2];
    const float* proj_w = (const float*)d_in[3];
    const float* proj_b = (const float*)d_in[4];
    const float* rpb    = (const float*)d_in[5];
    const int*   ridx   = (const int*)d_in[6];
    float* out = (float*)d_out;

    __half *xh, *qkvh, *vlo, *ctx, *wqh, *wph;
    float *biasm;
    cudaGetSymbolAddress((void**)&xh,    g_xh);
    cudaGetSymbolAddress((void**)&qkvh,  g_qkvh);
    cudaGetSymbolAddress((void**)&vlo,   g_vlo);
    cudaGetSymbolAddress((void**)&ctx,   g_ctx);
    cudaGetSymbolAddress((void**)&wqh,   g_wqh);
    cudaGetSymbolAddress((void**)&wph,   g_wph);
    cudaGetSymbolAddress((void**)&biasm, g_bias);

    static bool attr_set = false;
    if (!attr_set) {
        cudaFuncSetAttribute(gemm_f16<0>, cudaFuncAttributeMaxDynamicSharedMemorySize, GEMM_SMEM);
        cudaFuncSetAttribute(gemm_f16<1>, cudaFuncAttributeMaxDynamicSharedMemorySize, GEMM_SMEM);
        attr_set = true;
    }

    // 0) bias table
    bias_kernel<<<HEADS, 256>>>(rpb, ridx, biasm);

    // 1) fp16 conversions
    {
        int n4 = (M_TOT * DIM) / 4;
        split_h1<<<(n4 + 255) / 256, 256>>>(x, xh, n4);
        int w4 = (QKV_N * DIM) / 4;
        split_h1<<<(w4 + 255) / 256, 256>>>(qkv_w, wqh, w4);
        int p4 = (DIM * DIM) / 4;
        split_h1<<<(p4 + 255) / 256, 256>>>(proj_w, wph, p4);
    }

    // 2) QKV GEMM (1-term fp16) -> fp16 qkv (+ v_lo)
    {
        dim3 grid(QKV_N / 128, M_TOT / 128);   // (9, 1568)
        gemm_f16<1><<<grid, 256, GEMM_SMEM>>>(xh, wqh, qkv_b, nullptr, qkvh, vlo, QKV_N);
    }

    // 3) Attention
    {
        dim3 grid(B_WIN, HEADS);
        attn_kernel<<<grid, 128>>>(qkvh, vlo, biasm, ctx);
    }

    // 4) Projection GEMM (1-term fp16) -> fp32 out
    {
        dim3 grid(DIM / 128, M_TOT / 128);     // (3, 1568)
        gemm_f16<0><<<grid, 256, GEMM_SMEM>>>(ctx, wph, proj_b, out, nullptr, nullptr, DIM);
    }
}

// round 9
// speedup vs baseline: 4.1799x; 1.0320x over previous
#include <cuda_runtime.h>
#include <cuda_fp16.h>
#include <math.h>
#include <stdint.h>

// Problem constants
#define B_WIN 4096
#define N_TOK 49
#define DIM   384
#define HEADS 12
#define HD    32
#define M_TOT (B_WIN * N_TOK)     // 200704
#define QKV_N (3 * DIM)           // 1152
#define KTOT  384
#define SCALE 0.17677669529663687f

// ---------------------------------------------------------------------------
// Scratch (static device globals — allocation-guard safe)
// ---------------------------------------------------------------------------
__device__ __half  g_xh  [(size_t)M_TOT * DIM];
__device__ __half  g_qkvh[(size_t)M_TOT * QKV_N];   // q(scaled)|k|v_hi, fp16
__device__ __half  g_vlo [(size_t)M_TOT * DIM];     // v_lo fp16
__device__ __half  g_ctx [(size_t)M_TOT * DIM];     // attention output fp16
__device__ __half  g_wqh [(size_t)QKV_N * DIM];
__device__ __half  g_wph [(size_t)DIM * DIM];
__device__ float   g_biasf[HEADS * 4 * 32 * 32];    // fragment-layout bias

// ---------------------------------------------------------------------------
// PTX helpers (sm_80-compatible only)
// ---------------------------------------------------------------------------
__device__ __forceinline__ uint32_t smem_u32(const void* p) {
    uint32_t a;
    asm("{ .reg .u64 t; cvta.to.shared.u64 t, %1; cvt.u32.u64 %0, t; }" : "=r"(a) : "l"(p));
    return a;
}

#define CP_ASYNC16(dst, src) \
    asm volatile("cp.async.cg.shared.global [%0], [%1], 16;" :: "r"(dst), "l"(src))
#define CP_COMMIT() asm volatile("cp.async.commit_group;" ::: "memory")
#define CP_WAIT2()  asm volatile("cp.async.wait_group 2;" ::: "memory")

#define LDSM_X4(r0, r1, r2, r3, addr) \
    asm volatile("ldmatrix.sync.aligned.m8n8.x4.shared.b16 {%0,%1,%2,%3}, [%4];" \
        : "=r"(r0), "=r"(r1), "=r"(r2), "=r"(r3) : "r"(addr))

#define LDSM_X4T(r0, r1, r2, r3, addr) \
    asm volatile("ldmatrix.sync.aligned.m8n8.x4.trans.shared.b16 {%0,%1,%2,%3}, [%4];" \
        : "=r"(r0), "=r"(r1), "=r"(r2), "=r"(r3) : "r"(addr))

#define MMA_F16(d, a, b) \
    asm volatile("mma.sync.aligned.m16n8k16.row.col.f32.f16.f16.f32 " \
        "{%0,%1,%2,%3}, {%4,%5,%6,%7}, {%8,%9}, {%0,%1,%2,%3};" \
        : "+f"((d)[0]), "+f"((d)[1]), "+f"((d)[2]), "+f"((d)[3]) \
        : "r"((a)[0]), "r"((a)[1]), "r"((a)[2]), "r"((a)[3]), \
          "r"((b)[0]), "r"((b)[1]))

// ---------------------------------------------------------------------------
// Bias precompute in mma-fragment layout, padded with -1e30.
// biasf[((h*4 + w)*32 + lane)*32 + nf*4 + j]
// row = w*16 + (lane>>2) + (j>=2 ? 8 : 0); col = nf*8 + (lane&3)*2 + (j&1)
// ---------------------------------------------------------------------------
__global__ void bias_frag_kernel(const float* __restrict__ rpb,
                                 const int* __restrict__ ridx,
                                 float* __restrict__ bf)
{
    int h = blockIdx.x;
    int w = threadIdx.x >> 5;
    int lane = threadIdx.x & 31;
    float* dst = bf + ((size_t)(h * 4 + w) * 32 + lane) * 32;
    #pragma unroll
    for (int nf = 0; nf < 8; ++nf)
        #pragma unroll
        for (int j = 0; j < 4; ++j) {
            int row = w * 16 + (lane >> 2) + ((j >= 2) ? 8 : 0);
            int col = nf * 8 + (lane & 3) * 2 + (j & 1);
            dst[nf * 4 + j] = (row < N_TOK && col < N_TOK)
                ? rpb[ridx[row * N_TOK + col] * HEADS + h] : -1e30f;
        }
}

// ---------------------------------------------------------------------------
// Split: fp32 -> fp16
// ---------------------------------------------------------------------------
__global__ void split_h1(const float* __restrict__ src, __half* __restrict__ dst, int n4)
{
    int i = blockIdx.x * blockDim.x + threadIdx.x;
    if (i >= n4) return;
    float4 v = ((const float4*)src)[i];
    __half2* D = (__half2*)dst;
    D[2 * i]     = __floats2half2_rn(v.x, v.y);
    D[2 * i + 1] = __floats2half2_rn(v.z, v.w);
}

// ---------------------------------------------------------------------------
// Single-term fp16 GEMM: C[M,N] = A[M,384] @ W[N,384]^T + bias
// 128x128 tile, 256 thr, 4-stage cp.async, 2 CTAs/SM.  (at HMMA issue floor)
// EPI=0: fp32 out.  EPI=1: QKV epilogue (scale q cols, fp16 out + v_lo).
// ---------------------------------------------------------------------------
#define BK        32
#define NCHUNK    (KTOT / BK)            // 12
#define NSTAGE    4
#define ASTRIDE   80                     // bytes per 32-half row (64 + 16 pad)
#define HALF_B    (128 * ASTRIDE)        // 10240
#define STAGE_B   (2 * HALF_B)           // 20480 (A | B)
#define GEMM_SMEM (NSTAGE * STAGE_B)     // 81920

template<int EPI>
__global__ void __launch_bounds__(256, 2) gemm_f16(
    const __half* __restrict__ Ah, const __half* __restrict__ Bh,
    const float* __restrict__ bias,
    float* __restrict__ Cf, __half* __restrict__ Ch, __half* __restrict__ Vlo,
    int N)
{
    extern __shared__ char smem[];
    const uint32_t sb = smem_u32(smem);
    const int tid  = threadIdx.x;
    const int lane = tid & 31;
    const int wid  = tid >> 5;
    const int warp_m = wid & 1;
    const int warp_n = wid >> 1;
    const int bm = blockIdx.y * 128;
    const int bn = blockIdx.x * 128;

    float acc[4][4][4];
    #pragma unroll
    for (int i = 0; i < 4; ++i)
        #pragma unroll
        for (int j = 0; j < 4; ++j)
            #pragma unroll
            for (int r = 0; r < 4; ++r) acc[i][j][r] = 0.0f;

    auto load_chunk = [&](int stage, int kc) {
        #pragma unroll
        for (int t = 0; t < 2; ++t) {
            const __half* src = (t == 0) ? Ah : Bh;
            const int rbase = (t == 0) ? bm : bn;
            const uint32_t hoff = sb + (uint32_t)stage * STAGE_B + (uint32_t)t * HALF_B;
            #pragma unroll
            for (int it = 0; it < 2; ++it) {
                int idx = tid + it * 256;
                int row = idx >> 2;
                int c16 = idx & 3;
                const __half* g = src + (size_t)(rbase + row) * KTOT + kc + c16 * 8;
                uint32_t dst = hoff + (uint32_t)(row * ASTRIDE + c16 * 16);
                CP_ASYNC16(dst, g);
            }
        }
    };

    load_chunk(0, 0);      CP_COMMIT();
    load_chunk(1, BK);     CP_COMMIT();
    load_chunk(2, 2 * BK); CP_COMMIT();

    for (int c = 0; c < NCHUNK; ++c) {
        CP_WAIT2();
        __syncthreads();

        if (c + 3 < NCHUNK) load_chunk((c + 3) % NSTAGE, (c + 3) * BK);
        CP_COMMIT();

        const uint32_t base = sb + (uint32_t)(c % NSTAGE) * STAGE_B;
        #pragma unroll
        for (int ks = 0; ks < 2; ++ks) {
            const uint32_t koff = (uint32_t)(ks * 32) + ((lane >> 4) << 4);
            const uint32_t arow = (uint32_t)(warp_m * 64 + (lane & 15));
            const uint32_t brow = (uint32_t)(warp_n * 32 + (lane & 15));

            uint32_t ah[4][4], bh[4][2];
            #pragma unroll
            for (int mf = 0; mf < 4; ++mf) {
                uint32_t a = base + (arow + mf * 16) * ASTRIDE + koff;
                LDSM_X4(ah[mf][0], ah[mf][1], ah[mf][2], ah[mf][3], a);
            }
            #pragma unroll
            for (int g = 0; g < 2; ++g) {
                uint32_t a = base + HALF_B + (brow + g * 16) * ASTRIDE + koff;
                uint32_t r0, r1, r2, r3;
                LDSM_X4(r0, r1, r2, r3, a);
                bh[2 * g][0] = r0; bh[2 * g][1] = r2;
                bh[2 * g + 1][0] = r1; bh[2 * g + 1][1] = r3;
            }
            #pragma unroll
            for (int mf = 0; mf < 4; ++mf)
                #pragma unroll
                for (int nf = 0; nf < 4; ++nf)
                    MMA_F16(acc[mf][nf], ah[mf], bh[nf]);
        }
    }

    #pragma unroll
    for (int mf = 0; mf < 4; ++mf) {
        int row = bm + warp_m * 64 + mf * 16 + (lane >> 2);
        #pragma unroll
        for (int nf = 0; nf < 4; ++nf) {
            int col = bn + warp_n * 32 + nf * 8 + (lane & 3) * 2;
            float b0 = bias[col], b1 = bias[col + 1];
            #pragma unroll
            for (int hf = 0; hf < 2; ++hf) {
                int r = row + hf * 8;
                float v0 = acc[mf][nf][2 * hf + 0] + b0;
                float v1 = acc[mf][nf][2 * hf + 1] + b1;
                if (EPI == 0) {
                    *(float2*)(Cf + (size_t)r * N + col) = make_float2(v0, v1);
                } else {
                    if (col < DIM) { v0 *= SCALE; v1 *= SCALE; }
                    __half2 h2 = __floats2half2_rn(v0, v1);
                    *(__half2*)(Ch + (size_t)r * N + col) = h2;
                    if (col >= 2 * DIM) {
                        __half2 l2 = __floats2half2_rn(
                            v0 - __half2float(h2.x), v1 - __half2float(h2.y));
                        *(__half2*)(Vlo + (size_t)r * DIM + (col - 2 * DIM)) = l2;
                    }
                }
            }
        }
    }
}

// ---------------------------------------------------------------------------
// Tensorized attention, register softmax, fragment-layout bias,
// V via ldmatrix.trans (no smem scatter).
// ---------------------------------------------------------------------------
#define QK_STRIDE 40      // halves per row (32 data + 8 pad) = 80B
#define ROW_B     (QK_STRIDE * 2)

__global__ void __launch_bounds__(128) attn_kernel(
    const __half* __restrict__ qkv, const __half* __restrict__ vlo,
    const float* __restrict__ biasf,
    __half* __restrict__ ctx)
{
    const int b = blockIdx.x;
    const int h = blockIdx.y;
    const int tid = threadIdx.x;
    const int lane = tid & 31;
    const int w = tid >> 5;

    __shared__ __half qs [64 * QK_STRIDE];
    __shared__ __half kss[64 * QK_STRIDE];
    __shared__ __half vh [64 * QK_STRIDE];
    __shared__ __half vl [64 * QK_STRIDE];

    // zero token rows 49..63 of each buffer (u32 idx [980,1280))
    for (int i = tid; i < 300; i += 128) {
        ((uint32_t*)qs)[980 + i]  = 0;
        ((uint32_t*)kss)[980 + i] = 0;
        ((uint32_t*)vh)[980 + i]  = 0;
        ((uint32_t*)vl)[980 + i]  = 0;
    }
    __syncthreads();

    // vectorized loads: per token 16 uint4 chunks (q,k,vhi,vlo x4)
    for (int idx = tid; idx < N_TOK * 16; idx += 128) {
        int n  = idx >> 4;
        int r  = idx & 15;
        int t  = r >> 2;
        int c8 = (r & 3) * 8;
        size_t rowb = (size_t)(b * N_TOK + n);
        const __half* src;
        __half* dst;
        if (t < 3) {
            src = qkv + rowb * QKV_N + h * HD + t * DIM + c8;
            dst = (t == 0 ? qs : (t == 1 ? kss : vh)) + n * QK_STRIDE + c8;
        } else {
            src = vlo + rowb * DIM + h * HD + c8;
            dst = vl + n * QK_STRIDE + c8;
        }
        *(uint4*)dst = *(const uint4*)src;
    }
    __syncthreads();

    const uint32_t qb  = smem_u32(qs);
    const uint32_t kb  = smem_u32(kss);
    const uint32_t vhb = smem_u32(vh);
    const uint32_t vlb = smem_u32(vl);
    const int lrow = lane & 15;
    const int khi  = (lane >> 4) * 16;

    // ---- S = Q @ K^T (skip all-pad token tile nf=7) ----
    float accS[8][4];
    #pragma unroll
    for (int nf = 0; nf < 8; ++nf)
        #pragma unroll
        for (int r = 0; r < 4; ++r) accS[nf][r] = 0.0f;

    #pragma unroll
    for (int ki = 0; ki < 2; ++ki) {
        const uint32_t koff = ki * 32 + khi;
        uint32_t a[4];
        LDSM_X4(a[0], a[1], a[2], a[3], qb + (w * 16 + lrow) * ROW_B + koff);
        uint32_t bfr[8][2];
        #pragma unroll
        for (int g = 0; g < 4; ++g) {
            uint32_t r0, r1, r2, r3;
            LDSM_X4(r0, r1, r2, r3, kb + (g * 16 + lrow) * ROW_B + koff);
            bfr[2 * g][0] = r0; bfr[2 * g][1] = r2;
            bfr[2 * g + 1][0] = r1; bfr[2 * g + 1][1] = r3;
        }
        #pragma unroll
        for (int nf = 0; nf < 7; ++nf) MMA_F16(accS[nf], a, bfr[nf]);
    }

    // ---- bias add (fragment-layout, padded with -1e30) ----
    {
        const float4* bf4 = (const float4*)(biasf + ((size_t)(h * 4 + w) * 32 + lane) * 32);
        #pragma unroll
        for (int nf = 0; nf < 8; ++nf) {
            float4 bb = bf4[nf];
            accS[nf][0] += bb.x; accS[nf][1] += bb.y;
            accS[nf][2] += bb.z; accS[nf][3] += bb.w;
        }
    }

    // ---- register softmax (branch-free) ----
    float mA = -1e30f, mB = -1e30f;
    #pragma unroll
    for (int nf = 0; nf < 8; ++nf) {
        mA = fmaxf(mA, fmaxf(accS[nf][0], accS[nf][1]));
        mB = fmaxf(mB, fmaxf(accS[nf][2], accS[nf][3]));
    }
    mA = fmaxf(mA, __shfl_xor_sync(0xFFFFFFFF, mA, 1));
    mA = fmaxf(mA, __shfl_xor_sync(0xFFFFFFFF, mA, 2));
    mB = fmaxf(mB, __shfl_xor_sync(0xFFFFFFFF, mB, 1));
    mB = fmaxf(mB, __shfl_xor_sync(0xFFFFFFFF, mB, 2));

    float sA = 0.0f, sB = 0.0f;
    #pragma unroll
    for (int nf = 0; nf < 8; ++nf) {
        float e0 = __expf(accS[nf][0] - mA);
        float e1 = __expf(accS[nf][1] - mA);
        float e2 = __expf(accS[nf][2] - mB);
        float e3 = __expf(accS[nf][3] - mB);
        accS[nf][0] = e0; accS[nf][1] = e1;
        accS[nf][2] = e2; accS[nf][3] = e3;
        sA += e0 + e1; sB += e2 + e3;
    }
    sA += __shfl_xor_sync(0xFFFFFFFF, sA, 1);
    sA += __shfl_xor_sync(0xFFFFFFFF, sA, 2);
    sB += __shfl_xor_sync(0xFFFFFFFF, sB, 1);
    sB += __shfl_xor_sync(0xFFFFFFFF, sB, 2);
    const float invA = 1.0f / fmaxf(sA, 1e-30f);
    const float invB = 1.0f / fmaxf(sB, 1e-30f);
    #pragma unroll
    for (int nf = 0; nf < 8; ++nf) {
        accS[nf][0] *= invA; accS[nf][1] *= invA;
        accS[nf][2] *= invB; accS[nf][3] *= invB;
    }

    // ---- out = P @ V (V via ldmatrix.trans; fp16 hi/lo, 3 terms) ----
    float accO[4][4];
    #pragma unroll
    for (int nf = 0; nf < 4; ++nf)
        #pragma unroll
        for (int r = 0; r < 4; ++r) accO[nf][r] = 0.0f;

    const int vrow0 = (lane & 7) + ((lane & 16) >> 1);   // within 16-token chunk
    const int vcol0 = lane & 8;                          // dim-halves offset

    #pragma unroll
    for (int kt = 0; kt < 4; ++kt) {
        uint32_t aph[4], apl[4];
        #pragma unroll
        for (int q = 0; q < 4; ++q) {
            const int nf = 2 * kt + (q >> 1);
            const int j0 = (q & 1) * 2;
            float p0 = accS[nf][j0], p1 = accS[nf][j0 + 1];
            __half2 hi2 = __floats2half2_rn(p0, p1);
            __half2 lo2 = __floats2half2_rn(
                p0 - __half2float(hi2.x), p1 - __half2float(hi2.y));
            aph[q] = *(uint32_t*)&hi2;
            apl[q] = *(uint32_t*)&lo2;
        }
        uint32_t bvh[4][2], bvl[4][2];
        #pragma unroll
        for (int call = 0; call < 2; ++call) {
            uint32_t off = (uint32_t)(kt * 16 + vrow0) * ROW_B + (call * 16 + vcol0) * 2;
            uint32_t r0, r1, r2, r3;
            LDSM_X4T(r0, r1, r2, r3, vhb + off);
            bvh[2 * call][0] = r0; bvh[2 * call][1] = r2;
            bvh[2 * call + 1][0] = r1; bvh[2 * call + 1][1] = r3;
            LDSM_X4T(r0, r1, r2, r3, vlb + off);
            bvl[2 * call][0] = r0; bvl[2 * call][1] = r2;
            bvl[2 * call + 1][0] = r1; bvl[2 * call + 1][1] = r3;
        }
        #pragma unroll
        for (int nf = 0; nf < 4; ++nf) {
            MMA_F16(accO[nf], aph, bvh[nf]);
            MMA_F16(accO[nf], aph, bvl[nf]);
            MMA_F16(accO[nf], apl, bvh[nf]);
        }
    }

    // epilogue: single fp16 ctx
    const int rA = w * 16 + (lane >> 2);
    const int c0 = (lane & 3) * 2;
    #pragma unroll
    for (int half_i = 0; half_i < 2; ++half_i) {
        int row = rA + half_i * 8;
        if (row < N_TOK) {
            size_t obase = (size_t)(b * N_TOK + row) * DIM + h * HD;
            #pragma unroll
            for (int nf = 0; nf < 4; ++nf) {
                int d = nf * 8 + c0;
                *(__half2*)(ctx + obase + d) = __floats2half2_rn(
                    accO[nf][2 * half_i + 0], accO[nf][2 * half_i + 1]);
            }
        }
    }
}

// ---------------------------------------------------------------------------
extern "C" void kernel_launch(void* const* d_in, const int* in_sizes, int n_in,
                              void* d_out, int out_size)
{
    const float* x      = (const float*)d_in[0];
    const float* qkv_w  = (const float*)d_in[1];
    const float* qkv_b  = (const float*)d_in[2];
    const float* proj_w = (const float*)d_in[3];
    const float* proj_b = (const float*)d_in[4];
    const float* rpb    = (const float*)d_in[5];
    const int*   ridx   = (const int*)d_in[6];
    float* out = (float*)d_out;

    __half *xh, *qkvh, *vloP, *ctx, *wqh, *wph;
    float *biasf;
    cudaGetSymbolAddress((void**)&xh,    g_xh);
    cudaGetSymbolAddress((void**)&qkvh,  g_qkvh);
    cudaGetSymbolAddress((void**)&vloP,  g_vlo);
    cudaGetSymbolAddress((void**)&ctx,   g_ctx);
    cudaGetSymbolAddress((void**)&wqh,   g_wqh);
    cudaGetSymbolAddress((void**)&wph,   g_wph);
    cudaGetSymbolAddress((void**)&biasf, g_biasf);

    static bool attr_set = false;
    if (!attr_set) {
        cudaFuncSetAttribute(gemm_f16<0>, cudaFuncAttributeMaxDynamicSharedMemorySize, GEMM_SMEM);
        cudaFuncSetAttribute(gemm_f16<1>, cudaFuncAttributeMaxDynamicSharedMemorySize, GEMM_SMEM);
        attr_set = true;
    }

    // 0) fragment-layout bias table
    bias_frag_kernel<<<HEADS, 128>>>(rpb, ridx, biasf);

    // 1) fp16 conversions
    {
        int n4 = (M_TOT * DIM) / 4;
        split_h1<<<(n4 + 255) / 256, 256>>>(x, xh, n4);
        int w4 = (QKV_N * DIM) / 4;
        split_h1<<<(w4 + 255) / 256, 256>>>(qkv_w, wqh, w4);
        int p4 = (DIM * DIM) / 4;
        split_h1<<<(p4 + 255) / 256, 256>>>(proj_w, wph, p4);
    }

    // 2) QKV GEMM (1-term fp16) -> fp16 qkv (+ v_lo)
    {
        dim3 grid(QKV_N / 128, M_TOT / 128);   // (9, 1568)
        gemm_f16<1><<<grid, 256, GEMM_SMEM>>>(xh, wqh, qkv_b, nullptr, qkvh, vloP, QKV_N);
    }

    // 3) Attention
    {
        dim3 grid(B_WIN, HEADS);
        attn_kernel<<<grid, 128>>>(qkvh, vloP, biasf, ctx);
    }

    // 4) Projection GEMM (1-term fp16) -> fp32 out
    {
        dim3 grid(DIM / 128, M_TOT / 128);     // (3, 1568)
        gemm_f16<0><<<grid, 256, GEMM_SMEM>>>(ctx, wph, proj_b, out, nullptr, nullptr, DIM);
    }
}

// round 10
// speedup vs baseline: 4.5719x; 1.0938x over previous
#include <cuda_runtime.h>
#include <cuda_fp16.h>
#include <math.h>
#include <stdint.h>

// Problem constants
#define B_WIN 4096
#define N_TOK 49
#define DIM   384
#define HEADS 12
#define HD    32
#define M_TOT (B_WIN * N_TOK)     // 200704
#define QKV_N (3 * DIM)           // 1152
#define KTOT  384
#define SCALE 0.17677669529663687f

// ---------------------------------------------------------------------------
// Scratch (static device globals — allocation-guard safe)
// ---------------------------------------------------------------------------
__device__ __half  g_xh  [(size_t)M_TOT * DIM];
__device__ __half  g_qkvh[(size_t)M_TOT * QKV_N];   // q(scaled)|k|v, fp16
__device__ __half  g_ctx [(size_t)M_TOT * DIM];     // attention output fp16
__device__ __half  g_wqh [(size_t)QKV_N * DIM];
__device__ __half  g_wph [(size_t)DIM * DIM];
__device__ float   g_biasf[HEADS * 4 * 32 * 32];    // fragment-layout bias

// ---------------------------------------------------------------------------
// PTX helpers (sm_80-compatible only)
// ---------------------------------------------------------------------------
__device__ __forceinline__ uint32_t smem_u32(const void* p) {
    uint32_t a;
    asm("{ .reg .u64 t; cvta.to.shared.u64 t, %1; cvt.u32.u64 %0, t; }" : "=r"(a) : "l"(p));
    return a;
}

#define CP_ASYNC16(dst, src) \
    asm volatile("cp.async.cg.shared.global [%0], [%1], 16;" :: "r"(dst), "l"(src))
#define CP_COMMIT() asm volatile("cp.async.commit_group;" ::: "memory")
#define CP_WAIT2()  asm volatile("cp.async.wait_group 2;" ::: "memory")

#define LDSM_X4(r0, r1, r2, r3, addr) \
    asm volatile("ldmatrix.sync.aligned.m8n8.x4.shared.b16 {%0,%1,%2,%3}, [%4];" \
        : "=r"(r0), "=r"(r1), "=r"(r2), "=r"(r3) : "r"(addr))

#define LDSM_X4T(r0, r1, r2, r3, addr) \
    asm volatile("ldmatrix.sync.aligned.m8n8.x4.trans.shared.b16 {%0,%1,%2,%3}, [%4];" \
        : "=r"(r0), "=r"(r1), "=r"(r2), "=r"(r3) : "r"(addr))

#define MMA_F16(d, a, b) \
    asm volatile("mma.sync.aligned.m16n8k16.row.col.f32.f16.f16.f32 " \
        "{%0,%1,%2,%3}, {%4,%5,%6,%7}, {%8,%9}, {%0,%1,%2,%3};" \
        : "+f"((d)[0]), "+f"((d)[1]), "+f"((d)[2]), "+f"((d)[3]) \
        : "r"((a)[0]), "r"((a)[1]), "r"((a)[2]), "r"((a)[3]), \
          "r"((b)[0]), "r"((b)[1]))

// ---------------------------------------------------------------------------
// Bias precompute in mma-fragment layout, padded with -1e30.
// ---------------------------------------------------------------------------
__global__ void bias_frag_kernel(const float* __restrict__ rpb,
                                 const int* __restrict__ ridx,
                                 float* __restrict__ bf)
{
    int h = blockIdx.x;
    int w = threadIdx.x >> 5;
    int lane = threadIdx.x & 31;
    float* dst = bf + ((size_t)(h * 4 + w) * 32 + lane) * 32;
    #pragma unroll
    for (int nf = 0; nf < 8; ++nf)
        #pragma unroll
        for (int j = 0; j < 4; ++j) {
            int row = w * 16 + (lane >> 2) + ((j >= 2) ? 8 : 0);
            int col = nf * 8 + (lane & 3) * 2 + (j & 1);
            dst[nf * 4 + j] = (row < N_TOK && col < N_TOK)
                ? rpb[ridx[row * N_TOK + col] * HEADS + h] : -1e30f;
        }
}

// ---------------------------------------------------------------------------
// Split: fp32 -> fp16
// ---------------------------------------------------------------------------
__global__ void split_h1(const float* __restrict__ src, __half* __restrict__ dst, int n4)
{
    int i = blockIdx.x * blockDim.x + threadIdx.x;
    if (i >= n4) return;
    float4 v = ((const float4*)src)[i];
    __half2* D = (__half2*)dst;
    D[2 * i]     = __floats2half2_rn(v.x, v.y);
    D[2 * i + 1] = __floats2half2_rn(v.z, v.w);
}

// ---------------------------------------------------------------------------
// Single-term fp16 GEMM: C[M,N] = A[M,384] @ W[N,384]^T + bias
// 128x128 tile, 256 thr, 4-stage cp.async, 2 CTAs/SM. (HMMA issue floor)
// EPI=0: fp32 out.  EPI=1: QKV epilogue (scale q cols, fp16 out).
// ---------------------------------------------------------------------------
#define BK        32
#define NCHUNK    (KTOT / BK)            // 12
#define NSTAGE    4
#define ASTRIDE   80                     // bytes per 32-half row (64 + 16 pad)
#define HALF_B    (128 * ASTRIDE)        // 10240
#define STAGE_B   (2 * HALF_B)           // 20480 (A | B)
#define GEMM_SMEM (NSTAGE * STAGE_B)     // 81920

template<int EPI>
__global__ void __launch_bounds__(256, 2) gemm_f16(
    const __half* __restrict__ Ah, const __half* __restrict__ Bh,
    const float* __restrict__ bias,
    float* __restrict__ Cf, __half* __restrict__ Ch,
    int N)
{
    extern __shared__ char smem[];
    const uint32_t sb = smem_u32(smem);
    const int tid  = threadIdx.x;
    const int lane = tid & 31;
    const int wid  = tid >> 5;
    const int warp_m = wid & 1;
    const int warp_n = wid >> 1;
    const int bm = blockIdx.y * 128;
    const int bn = blockIdx.x * 128;

    float acc[4][4][4];
    #pragma unroll
    for (int i = 0; i < 4; ++i)
        #pragma unroll
        for (int j = 0; j < 4; ++j)
            #pragma unroll
            for (int r = 0; r < 4; ++r) acc[i][j][r] = 0.0f;

    auto load_chunk = [&](int stage, int kc) {
        #pragma unroll
        for (int t = 0; t < 2; ++t) {
            const __half* src = (t == 0) ? Ah : Bh;
            const int rbase = (t == 0) ? bm : bn;
            const uint32_t hoff = sb + (uint32_t)stage * STAGE_B + (uint32_t)t * HALF_B;
            #pragma unroll
            for (int it = 0; it < 2; ++it) {
                int idx = tid + it * 256;
                int row = idx >> 2;
                int c16 = idx & 3;
                const __half* g = src + (size_t)(rbase + row) * KTOT + kc + c16 * 8;
                uint32_t dst = hoff + (uint32_t)(row * ASTRIDE + c16 * 16);
                CP_ASYNC16(dst, g);
            }
        }
    };

    load_chunk(0, 0);      CP_COMMIT();
    load_chunk(1, BK);     CP_COMMIT();
    load_chunk(2, 2 * BK); CP_COMMIT();

    for (int c = 0; c < NCHUNK; ++c) {
        CP_WAIT2();
        __syncthreads();

        if (c + 3 < NCHUNK) load_chunk((c + 3) % NSTAGE, (c + 3) * BK);
        CP_COMMIT();

        const uint32_t base = sb + (uint32_t)(c % NSTAGE) * STAGE_B;
        #pragma unroll
        for (int ks = 0; ks < 2; ++ks) {
            const uint32_t koff = (uint32_t)(ks * 32) + ((lane >> 4) << 4);
            const uint32_t arow = (uint32_t)(warp_m * 64 + (lane & 15));
            const uint32_t brow = (uint32_t)(warp_n * 32 + (lane & 15));

            uint32_t ah[4][4], bh[4][2];
            #pragma unroll
            for (int mf = 0; mf < 4; ++mf) {
                uint32_t a = base + (arow + mf * 16) * ASTRIDE + koff;
                LDSM_X4(ah[mf][0], ah[mf][1], ah[mf][2], ah[mf][3], a);
            }
            #pragma unroll
            for (int g = 0; g < 2; ++g) {
                uint32_t a = base + HALF_B + (brow + g * 16) * ASTRIDE + koff;
                uint32_t r0, r1, r2, r3;
                LDSM_X4(r0, r1, r2, r3, a);
                bh[2 * g][0] = r0; bh[2 * g][1] = r2;
                bh[2 * g + 1][0] = r1; bh[2 * g + 1][1] = r3;
            }
            #pragma unroll
            for (int mf = 0; mf < 4; ++mf)
                #pragma unroll
                for (int nf = 0; nf < 4; ++nf)
                    MMA_F16(acc[mf][nf], ah[mf], bh[nf]);
        }
    }

    #pragma unroll
    for (int mf = 0; mf < 4; ++mf) {
        int row = bm + warp_m * 64 + mf * 16 + (lane >> 2);
        #pragma unroll
        for (int nf = 0; nf < 4; ++nf) {
            int col = bn + warp_n * 32 + nf * 8 + (lane & 3) * 2;
            float b0 = bias[col], b1 = bias[col + 1];
            #pragma unroll
            for (int hf = 0; hf < 2; ++hf) {
                int r = row + hf * 8;
                float v0 = acc[mf][nf][2 * hf + 0] + b0;
                float v1 = acc[mf][nf][2 * hf + 1] + b1;
                if (EPI == 0) {
                    *(float2*)(Cf + (size_t)r * N + col) = make_float2(v0, v1);
                } else {
                    if (col < DIM) { v0 *= SCALE; v1 *= SCALE; }
                    *(__half2*)(Ch + (size_t)r * N + col) = __floats2half2_rn(v0, v1);
                }
            }
        }
    }
}

// ---------------------------------------------------------------------------
// Attention: 2 heads per CTA, 256 threads (8 warps = 2 heads x 4 warps).
// Coalesced 128B loads (adjacent heads). PV single-term fp16.
// ---------------------------------------------------------------------------
#define QK_STRIDE 40      // halves per row (32 data + 8 pad) = 80B
#define ROW_B     (QK_STRIDE * 2)
#define HBUF      (64 * QK_STRIDE)   // halves per head-buffer (2560)

__global__ void __launch_bounds__(256) attn_kernel(
    const __half* __restrict__ qkv,
    const float* __restrict__ biasf,
    __half* __restrict__ ctx)
{
    const int b  = blockIdx.x;
    const int h0 = blockIdx.y * 2;           // first head of the pair
    const int tid = threadIdx.x;
    const int lane = tid & 31;
    const int w  = tid >> 5;
    const int hh = w >> 2;                   // head within pair (0/1)
    const int ww = w & 3;                    // warp within head
    const int h  = h0 + hh;

    __shared__ __half qs [2 * HBUF];
    __shared__ __half kss[2 * HBUF];
    __shared__ __half vs [2 * HBUF];

    // zero token rows 49..63 of each head-buffer
    // (u32 idx within a head-buffer: [980, 1280); buffer 1 starts at 1280)
    for (int i = tid; i < 300; i += 256) {
        ((uint32_t*)qs)[980 + i]  = 0; ((uint32_t*)qs)[2260 + i]  = 0;
        ((uint32_t*)kss)[980 + i] = 0; ((uint32_t*)kss)[2260 + i] = 0;
        ((uint32_t*)vs)[980 + i]  = 0; ((uint32_t*)vs)[2260 + i]  = 0;
    }
    __syncthreads();

    // loads: per token, 3 tensors x 128B (both heads adjacent) = 24 uint4
    for (int idx = tid; idx < N_TOK * 24; idx += 256) {
        int n = idx / 24;
        int r = idx - n * 24;
        int t = r >> 3;                      // 0=q 1=k 2=v
        int s = r & 7;                       // 16B chunk within 128B pair-slice
        const __half* src = qkv + (size_t)(b * N_TOK + n) * QKV_N
                          + t * DIM + h0 * HD + s * 8;
        __half* buf = (t == 0) ? qs : (t == 1) ? kss : vs;
        int hh2 = s >> 2;
        int c8  = (s & 3) * 8;
        *(uint4*)(buf + hh2 * HBUF + n * QK_STRIDE + c8) = *(const uint4*)src;
    }
    __syncthreads();

    const uint32_t qb = smem_u32(qs)  + hh * (HBUF * 2);
    const uint32_t kb = smem_u32(kss) + hh * (HBUF * 2);
    const uint32_t vb = smem_u32(vs)  + hh * (HBUF * 2);
    const int lrow = lane & 15;
    const int khi  = (lane >> 4) * 16;

    // ---- S = Q @ K^T (skip all-pad token tile nf=7) ----
    float accS[8][4];
    #pragma unroll
    for (int nf = 0; nf < 8; ++nf)
        #pragma unroll
        for (int r = 0; r < 4; ++r) accS[nf][r] = 0.0f;

    #pragma unroll
    for (int ki = 0; ki < 2; ++ki) {
        const uint32_t koff = ki * 32 + khi;
        uint32_t a[4];
        LDSM_X4(a[0], a[1], a[2], a[3], qb + (ww * 16 + lrow) * ROW_B + koff);
        uint32_t bfr[8][2];
        #pragma unroll
        for (int g = 0; g < 4; ++g) {
            uint32_t r0, r1, r2, r3;
            LDSM_X4(r0, r1, r2, r3, kb + (g * 16 + lrow) * ROW_B + koff);
            bfr[2 * g][0] = r0; bfr[2 * g][1] = r2;
            bfr[2 * g + 1][0] = r1; bfr[2 * g + 1][1] = r3;
        }
        #pragma unroll
        for (int nf = 0; nf < 7; ++nf) MMA_F16(accS[nf], a, bfr[nf]);
    }

    // ---- bias add (fragment layout, pads = -1e30) ----
    {
        const float4* bf4 = (const float4*)(biasf + ((size_t)(h * 4 + ww) * 32 + lane) * 32);
        #pragma unroll
        for (int nf = 0; nf < 8; ++nf) {
            float4 bb = bf4[nf];
            accS[nf][0] += bb.x; accS[nf][1] += bb.y;
            accS[nf][2] += bb.z; accS[nf][3] += bb.w;
        }
    }

    // ---- register softmax ----
    float mA = -1e30f, mB = -1e30f;
    #pragma unroll
    for (int nf = 0; nf < 8; ++nf) {
        mA = fmaxf(mA, fmaxf(accS[nf][0], accS[nf][1]));
        mB = fmaxf(mB, fmaxf(accS[nf][2], accS[nf][3]));
    }
    mA = fmaxf(mA, __shfl_xor_sync(0xFFFFFFFF, mA, 1));
    mA = fmaxf(mA, __shfl_xor_sync(0xFFFFFFFF, mA, 2));
    mB = fmaxf(mB, __shfl_xor_sync(0xFFFFFFFF, mB, 1));
    mB = fmaxf(mB, __shfl_xor_sync(0xFFFFFFFF, mB, 2));

    float sA = 0.0f, sB = 0.0f;
    #pragma unroll
    for (int nf = 0; nf < 8; ++nf) {
        float e0 = __expf(accS[nf][0] - mA);
        float e1 = __expf(accS[nf][1] - mA);
        float e2 = __expf(accS[nf][2] - mB);
        float e3 = __expf(accS[nf][3] - mB);
        accS[nf][0] = e0; accS[nf][1] = e1;
        accS[nf][2] = e2; accS[nf][3] = e3;
        sA += e0 + e1; sB += e2 + e3;
    }
    sA += __shfl_xor_sync(0xFFFFFFFF, sA, 1);
    sA += __shfl_xor_sync(0xFFFFFFFF, sA, 2);
    sB += __shfl_xor_sync(0xFFFFFFFF, sB, 1);
    sB += __shfl_xor_sync(0xFFFFFFFF, sB, 2);
    const float invA = 1.0f / fmaxf(sA, 1e-30f);
    const float invB = 1.0f / fmaxf(sB, 1e-30f);
    #pragma unroll
    for (int nf = 0; nf < 8; ++nf) {
        accS[nf][0] *= invA; accS[nf][1] *= invA;
        accS[nf][2] *= invB; accS[nf][3] *= invB;
    }

    // ---- out = P @ V (single fp16 term; V via ldmatrix.trans) ----
    float accO[4][4];
    #pragma unroll
    for (int nf = 0; nf < 4; ++nf)
        #pragma unroll
        for (int r = 0; r < 4; ++r) accO[nf][r] = 0.0f;

    const int vrow0 = (lane & 7) + ((lane & 16) >> 1);
    const int vcol0 = lane & 8;

    #pragma unroll
    for (int kt = 0; kt < 4; ++kt) {
        uint32_t aph[4];
        #pragma unroll
        for (int q = 0; q < 4; ++q) {
            const int nf = 2 * kt + (q >> 1);
            const int j0 = (q & 1) * 2;
            __half2 hi2 = __floats2half2_rn(accS[nf][j0], accS[nf][j0 + 1]);
            aph[q] = *(uint32_t*)&hi2;
        }
        uint32_t bvh[4][2];
        #pragma unroll
        for (int call = 0; call < 2; ++call) {
            uint32_t off = (uint32_t)(kt * 16 + vrow0) * ROW_B + (call * 16 + vcol0) * 2;
            uint32_t r0, r1, r2, r3;
            LDSM_X4T(r0, r1, r2, r3, vb + off);
            bvh[2 * call][0] = r0; bvh[2 * call][1] = r2;
            bvh[2 * call + 1][0] = r1; bvh[2 * call + 1][1] = r3;
        }
        #pragma unroll
        for (int nf = 0; nf < 4; ++nf)
            MMA_F16(accO[nf], aph, bvh[nf]);
    }

    // epilogue: single fp16 ctx
    const int rA = ww * 16 + (lane >> 2);
    const int c0 = (lane & 3) * 2;
    #pragma unroll
    for (int half_i = 0; half_i < 2; ++half_i) {
        int row = rA + half_i * 8;
        if (row < N_TOK) {
            size_t obase = (size_t)(b * N_TOK + row) * DIM + h * HD;
            #pragma unroll
            for (int nf = 0; nf < 4; ++nf) {
                int d = nf * 8 + c0;
                *(__half2*)(ctx + obase + d) = __floats2half2_rn(
                    accO[nf][2 * half_i + 0], accO[nf][2 * half_i + 1]);
            }
        }
    }
}

// ---------------------------------------------------------------------------
extern "C" void kernel_launch(void* const* d_in, const int* in_sizes, int n_in,
                              void* d_out, int out_size)
{
    const float* x      = (const float*)d_in[0];
    const float* qkv_w  = (const float*)d_in[1];
    const float* qkv_b  = (const float*)d_in[2];
    const float* proj_w = (const float*)d_in[3];
    const float* proj_b = (const float*)d_in[4];
    const float* rpb    = (const float*)d_in[5];
    const int*   ridx   = (const int*)d_in[6];
    float* out = (float*)d_out;

    __half *xh, *qkvh, *ctx, *wqh, *wph;
    float *biasf;
    cudaGetSymbolAddress((void**)&xh,    g_xh);
    cudaGetSymbolAddress((void**)&qkvh,  g_qkvh);
    cudaGetSymbolAddress((void**)&ctx,   g_ctx);
    cudaGetSymbolAddress((void**)&wqh,   g_wqh);
    cudaGetSymbolAddress((void**)&wph,   g_wph);
    cudaGetSymbolAddress((void**)&biasf, g_biasf);

    static bool attr_set = false;
    if (!attr_set) {
        cudaFuncSetAttribute(gemm_f16<0>, cudaFuncAttributeMaxDynamicSharedMemorySize, GEMM_SMEM);
        cudaFuncSetAttribute(gemm_f16<1>, cudaFuncAttributeMaxDynamicSharedMemorySize, GEMM_SMEM);
        attr_set = true;
    }

    // 0) fragment-layout bias table
    bias_frag_kernel<<<HEADS, 128>>>(rpb, ridx, biasf);

    // 1) fp16 conversions
    {
        int n4 = (M_TOT * DIM) / 4;
        split_h1<<<(n4 + 255) / 256, 256>>>(x, xh, n4);
        int w4 = (QKV_N * DIM) / 4;
        split_h1<<<(w4 + 255) / 256, 256>>>(qkv_w, wqh, w4);
        int p4 = (DIM * DIM) / 4;
        split_h1<<<(p4 + 255) / 256, 256>>>(proj_w, wph, p4);
    }

    // 2) QKV GEMM (1-term fp16) -> fp16 qkv (q pre-scaled)
    {
        dim3 grid(QKV_N / 128, M_TOT / 128);   // (9, 1568)
        gemm_f16<1><<<grid, 256, GEMM_SMEM>>>(xh, wqh, qkv_b, nullptr, qkvh, QKV_N);
    }

    // 3) Attention (2 heads per CTA)
    {
        dim3 grid(B_WIN, HEADS / 2);           // (4096, 6)
        attn_kernel<<<grid, 256>>>(qkvh, biasf, ctx);
    }

    // 4) Projection GEMM (1-term fp16) -> fp32 out
    {
        dim3 grid(DIM / 128, M_TOT / 128);     // (3, 1568)
        gemm_f16<0><<<grid, 256, GEMM_SMEM>>>(ctx, wph, proj_b, out, nullptr, DIM);
    }
}

// round 11
// speedup vs baseline: 4.6883x; 1.0255x over previous
#include <cuda_runtime.h>
#include <cuda_fp16.h>
#include <math.h>
#include <stdint.h>

// Problem constants
#define B_WIN 4096
#define N_TOK 49
#define DIM   384
#define HEADS 12
#define HD    32
#define M_TOT (B_WIN * N_TOK)     // 200704
#define QKV_N (3 * DIM)           // 1152
#define KTOT  384
#define SCALE 0.17677669529663687f

// ---------------------------------------------------------------------------
// Scratch (static device globals — allocation-guard safe)
// ---------------------------------------------------------------------------
__device__ __half  g_xh  [(size_t)M_TOT * DIM];
__device__ __half  g_qkvh[(size_t)M_TOT * QKV_N];   // q(scaled)|k|v, fp16
__device__ __half  g_ctx [(size_t)M_TOT * DIM];     // attention output fp16
__device__ __half  g_wqh [(size_t)QKV_N * DIM];
__device__ __half  g_wph [(size_t)DIM * DIM];
__device__ float   g_biasf[HEADS * 4 * 32 * 32];    // fragment-layout bias

// ---------------------------------------------------------------------------
// PTX helpers (sm_80-compatible only)
// ---------------------------------------------------------------------------
__device__ __forceinline__ uint32_t smem_u32(const void* p) {
    uint32_t a;
    asm("{ .reg .u64 t; cvta.to.shared.u64 t, %1; cvt.u32.u64 %0, t; }" : "=r"(a) : "l"(p));
    return a;
}

#define CP_ASYNC16(dst, src) \
    asm volatile("cp.async.cg.shared.global [%0], [%1], 16;" :: "r"(dst), "l"(src))
#define CP_COMMIT() asm volatile("cp.async.commit_group;" ::: "memory")
#define CP_WAIT0()  asm volatile("cp.async.wait_group 0;" ::: "memory")
#define CP_WAIT2()  asm volatile("cp.async.wait_group 2;" ::: "memory")

#define LDSM_X4(r0, r1, r2, r3, addr) \
    asm volatile("ldmatrix.sync.aligned.m8n8.x4.shared.b16 {%0,%1,%2,%3}, [%4];" \
        : "=r"(r0), "=r"(r1), "=r"(r2), "=r"(r3) : "r"(addr))

#define LDSM_X4T(r0, r1, r2, r3, addr) \
    asm volatile("ldmatrix.sync.aligned.m8n8.x4.trans.shared.b16 {%0,%1,%2,%3}, [%4];" \
        : "=r"(r0), "=r"(r1), "=r"(r2), "=r"(r3) : "r"(addr))

#define MMA_F16(d, a, b) \
    asm volatile("mma.sync.aligned.m16n8k16.row.col.f32.f16.f16.f32 " \
        "{%0,%1,%2,%3}, {%4,%5,%6,%7}, {%8,%9}, {%0,%1,%2,%3};" \
        : "+f"((d)[0]), "+f"((d)[1]), "+f"((d)[2]), "+f"((d)[3]) \
        : "r"((a)[0]), "r"((a)[1]), "r"((a)[2]), "r"((a)[3]), \
          "r"((b)[0]), "r"((b)[1]))

// ---------------------------------------------------------------------------
// Bias precompute in mma-fragment layout, padded with -1e30.
// ---------------------------------------------------------------------------
__global__ void bias_frag_kernel(const float* __restrict__ rpb,
                                 const int* __restrict__ ridx,
                                 float* __restrict__ bf)
{
    int h = blockIdx.x;
    int w = threadIdx.x >> 5;
    int lane = threadIdx.x & 31;
    float* dst = bf + ((size_t)(h * 4 + w) * 32 + lane) * 32;
    #pragma unroll
    for (int nf = 0; nf < 8; ++nf)
        #pragma unroll
        for (int j = 0; j < 4; ++j) {
            int row = w * 16 + (lane >> 2) + ((j >= 2) ? 8 : 0);
            int col = nf * 8 + (lane & 3) * 2 + (j & 1);
            dst[nf * 4 + j] = (row < N_TOK && col < N_TOK)
                ? rpb[ridx[row * N_TOK + col] * HEADS + h] : -1e30f;
        }
}

// ---------------------------------------------------------------------------
// Split: fp32 -> fp16
// ---------------------------------------------------------------------------
__global__ void split_h1(const float* __restrict__ src, __half* __restrict__ dst, int n4)
{
    int i = blockIdx.x * blockDim.x + threadIdx.x;
    if (i >= n4) return;
    float4 v = ((const float4*)src)[i];
    __half2* D = (__half2*)dst;
    D[2 * i]     = __floats2half2_rn(v.x, v.y);
    D[2 * i + 1] = __floats2half2_rn(v.z, v.w);
}

// ---------------------------------------------------------------------------
// Single-term fp16 GEMM: C[M,N] = A[M,384] @ W[N,384]^T + bias
// 128x128 tile, 256 thr, 4-stage cp.async, 2 CTAs/SM. (HMMA issue floor)
// EPI=0: fp32 out.  EPI=1: QKV epilogue (scale q cols, fp16 out).
// ---------------------------------------------------------------------------
#define BK        32
#define NCHUNK    (KTOT / BK)            // 12
#define NSTAGE    4
#define ASTRIDE   80                     // bytes per 32-half row (64 + 16 pad)
#define HALF_B    (128 * ASTRIDE)        // 10240
#define STAGE_B   (2 * HALF_B)           // 20480 (A | B)
#define GEMM_SMEM (NSTAGE * STAGE_B)     // 81920

template<int EPI>
__global__ void __launch_bounds__(256, 2) gemm_f16(
    const __half* __restrict__ Ah, const __half* __restrict__ Bh,
    const float* __restrict__ bias,
    float* __restrict__ Cf, __half* __restrict__ Ch,
    int N)
{
    extern __shared__ char smem[];
    const uint32_t sb = smem_u32(smem);
    const int tid  = threadIdx.x;
    const int lane = tid & 31;
    const int wid  = tid >> 5;
    const int warp_m = wid & 1;
    const int warp_n = wid >> 1;
    const int bm = blockIdx.y * 128;
    const int bn = blockIdx.x * 128;

    float acc[4][4][4];
    #pragma unroll
    for (int i = 0; i < 4; ++i)
        #pragma unroll
        for (int j = 0; j < 4; ++j)
            #pragma unroll
            for (int r = 0; r < 4; ++r) acc[i][j][r] = 0.0f;

    auto load_chunk = [&](int stage, int kc) {
        #pragma unroll
        for (int t = 0; t < 2; ++t) {
            const __half* src = (t == 0) ? Ah : Bh;
            const int rbase = (t == 0) ? bm : bn;
            const uint32_t hoff = sb + (uint32_t)stage * STAGE_B + (uint32_t)t * HALF_B;
            #pragma unroll
            for (int it = 0; it < 2; ++it) {
                int idx = tid + it * 256;
                int row = idx >> 2;
                int c16 = idx & 3;
                const __half* g = src + (size_t)(rbase + row) * KTOT + kc + c16 * 8;
                uint32_t dst = hoff + (uint32_t)(row * ASTRIDE + c16 * 16);
                CP_ASYNC16(dst, g);
            }
        }
    };

    load_chunk(0, 0);      CP_COMMIT();
    load_chunk(1, BK);     CP_COMMIT();
    load_chunk(2, 2 * BK); CP_COMMIT();

    for (int c = 0; c < NCHUNK; ++c) {
        CP_WAIT2();
        __syncthreads();

        if (c + 3 < NCHUNK) load_chunk((c + 3) % NSTAGE, (c + 3) * BK);
        CP_COMMIT();

        const uint32_t base = sb + (uint32_t)(c % NSTAGE) * STAGE_B;
        #pragma unroll
        for (int ks = 0; ks < 2; ++ks) {
            const uint32_t koff = (uint32_t)(ks * 32) + ((lane >> 4) << 4);
            const uint32_t arow = (uint32_t)(warp_m * 64 + (lane & 15));
            const uint32_t brow = (uint32_t)(warp_n * 32 + (lane & 15));

            uint32_t ah[4][4], bh[4][2];
            #pragma unroll
            for (int mf = 0; mf < 4; ++mf) {
                uint32_t a = base + (arow + mf * 16) * ASTRIDE + koff;
                LDSM_X4(ah[mf][0], ah[mf][1], ah[mf][2], ah[mf][3], a);
            }
            #pragma unroll
            for (int g = 0; g < 2; ++g) {
                uint32_t a = base + HALF_B + (brow + g * 16) * ASTRIDE + koff;
                uint32_t r0, r1, r2, r3;
                LDSM_X4(r0, r1, r2, r3, a);
                bh[2 * g][0] = r0; bh[2 * g][1] = r2;
                bh[2 * g + 1][0] = r1; bh[2 * g + 1][1] = r3;
            }
            #pragma unroll
            for (int mf = 0; mf < 4; ++mf)
                #pragma unroll
                for (int nf = 0; nf < 4; ++nf)
                    MMA_F16(acc[mf][nf], ah[mf], bh[nf]);
        }
    }

    #pragma unroll
    for (int mf = 0; mf < 4; ++mf) {
        int row = bm + warp_m * 64 + mf * 16 + (lane >> 2);
        #pragma unroll
        for (int nf = 0; nf < 4; ++nf) {
            int col = bn + warp_n * 32 + nf * 8 + (lane & 3) * 2;
            float b0 = bias[col], b1 = bias[col + 1];
            #pragma unroll
            for (int hf = 0; hf < 2; ++hf) {
                int r = row + hf * 8;
                float v0 = acc[mf][nf][2 * hf + 0] + b0;
                float v1 = acc[mf][nf][2 * hf + 1] + b1;
                if (EPI == 0) {
                    *(float2*)(Cf + (size_t)r * N + col) = make_float2(v0, v1);
                } else {
                    if (col < DIM) { v0 *= SCALE; v1 *= SCALE; }
                    *(__half2*)(Ch + (size_t)r * N + col) = __floats2half2_rn(v0, v1);
                }
            }
        }
    }
}

// ---------------------------------------------------------------------------
// Attention v3: 8 windows x 2 heads per CTA, 256 threads, cp.async
// double-buffered across windows. PV single-term fp16.
// smem per stage: 3 tensors x 2 heads x 5120B = 30720B; 2 stages = 61440B.
// ---------------------------------------------------------------------------
#define NW        8
#define QK_STRIDE 40                     // halves per row (32 data + 8 pad)
#define ROW_B     (QK_STRIDE * 2)        // 80 bytes
#define HBUF_B    (64 * ROW_B)           // 5120 bytes per head-buffer
#define TEN_B     (2 * HBUF_B)           // 10240 bytes per tensor (2 heads)
#define ASTG_B    (3 * TEN_B)            // 30720 bytes per stage
#define ATTN_SMEM (2 * ASTG_B)           // 61440

__global__ void __launch_bounds__(256, 2) attn_kernel(
    const __half* __restrict__ qkv,
    const float* __restrict__ biasf,
    __half* __restrict__ ctx)
{
    extern __shared__ char smem[];
    const uint32_t sb = smem_u32(smem);
    const int b0 = blockIdx.x * NW;
    const int h0 = blockIdx.y * 2;
    const int tid = threadIdx.x;
    const int lane = tid & 31;
    const int w  = tid >> 5;
    const int hh = w >> 2;
    const int ww = w & 3;
    const int h  = h0 + hh;

    // zero pad token rows 49..63 once, in both stages (loads never touch them)
    // per head-buffer: bytes [49*80, 64*80) = [3920, 5120) -> 300 u32 per buffer
    for (int i = tid; i < 300; i += 256) {
        #pragma unroll
        for (int s = 0; s < 2; ++s)
            #pragma unroll
            for (int t = 0; t < 3; ++t)
                #pragma unroll
                for (int hb = 0; hb < 2; ++hb)
                    *(uint32_t*)(smem + s * ASTG_B + t * TEN_B + hb * HBUF_B
                                 + 3920 + i * 4) = 0;
    }

    // prefetch: window wi -> stage (wi & 1)
    auto prefetch = [&](int wi) {
        const uint32_t stg = sb + (uint32_t)(wi & 1) * ASTG_B;
        const size_t wb = (size_t)(b0 + wi) * N_TOK;
        for (int idx = tid; idx < N_TOK * 24; idx += 256) {
            int n = idx / 24;
            int r = idx - n * 24;
            int t = r >> 3;                  // 0=q 1=k 2=v
            int s = r & 7;                   // 16B chunk within 128B pair-slice
            const __half* src = qkv + (wb + n) * QKV_N + t * DIM + h0 * HD + s * 8;
            uint32_t dst = stg + (uint32_t)(t * TEN_B + (s >> 2) * HBUF_B
                         + n * ROW_B + (s & 3) * 16);
            CP_ASYNC16(dst, src);
        }
    };

    prefetch(0);
    CP_COMMIT();

    const int lrow = lane & 15;
    const int khi  = (lane >> 4) * 16;
    const int vrow0 = (lane & 7) + ((lane & 16) >> 1);
    const int vcol0 = lane & 8;
    const int rA = ww * 16 + (lane >> 2);
    const int c0 = (lane & 3) * 2;
    const float4* bf4 = (const float4*)(biasf + ((size_t)(h * 4 + ww) * 32 + lane) * 32);

    for (int it = 0; it < NW; ++it) {
        CP_WAIT0();
        __syncthreads();               // data for `it` visible; compute(it-1) done

        if (it + 1 < NW) prefetch(it + 1);
        CP_COMMIT();

        const uint32_t stg = sb + (uint32_t)(it & 1) * ASTG_B;
        const uint32_t qb = stg + hh * HBUF_B;
        const uint32_t kb = stg + TEN_B + hh * HBUF_B;
        const uint32_t vb = stg + 2 * TEN_B + hh * HBUF_B;

        // ---- S = Q @ K^T (skip all-pad token tile nf=7) ----
        float accS[8][4];
        #pragma unroll
        for (int nf = 0; nf < 8; ++nf)
            #pragma unroll
            for (int r = 0; r < 4; ++r) accS[nf][r] = 0.0f;

        #pragma unroll
        for (int ki = 0; ki < 2; ++ki) {
            const uint32_t koff = ki * 32 + khi;
            uint32_t a[4];
            LDSM_X4(a[0], a[1], a[2], a[3], qb + (ww * 16 + lrow) * ROW_B + koff);
            uint32_t bfr[8][2];
            #pragma unroll
            for (int g = 0; g < 4; ++g) {
                uint32_t r0, r1, r2, r3;
                LDSM_X4(r0, r1, r2, r3, kb + (g * 16 + lrow) * ROW_B + koff);
                bfr[2 * g][0] = r0; bfr[2 * g][1] = r2;
                bfr[2 * g + 1][0] = r1; bfr[2 * g + 1][1] = r3;
            }
            #pragma unroll
            for (int nf = 0; nf < 7; ++nf) MMA_F16(accS[nf], a, bfr[nf]);
        }

        // ---- bias add (fragment layout, pads = -1e30; L2-hot) ----
        #pragma unroll
        for (int nf = 0; nf < 8; ++nf) {
            float4 bb = bf4[nf];
            accS[nf][0] += bb.x; accS[nf][1] += bb.y;
            accS[nf][2] += bb.z; accS[nf][3] += bb.w;
        }

        // ---- register softmax ----
        float mA = -1e30f, mB = -1e30f;
        #pragma unroll
        for (int nf = 0; nf < 8; ++nf) {
            mA = fmaxf(mA, fmaxf(accS[nf][0], accS[nf][1]));
            mB = fmaxf(mB, fmaxf(accS[nf][2], accS[nf][3]));
        }
        mA = fmaxf(mA, __shfl_xor_sync(0xFFFFFFFF, mA, 1));
        mA = fmaxf(mA, __shfl_xor_sync(0xFFFFFFFF, mA, 2));
        mB = fmaxf(mB, __shfl_xor_sync(0xFFFFFFFF, mB, 1));
        mB = fmaxf(mB, __shfl_xor_sync(0xFFFFFFFF, mB, 2));

        float sA = 0.0f, sB = 0.0f;
        #pragma unroll
        for (int nf = 0; nf < 8; ++nf) {
            float e0 = __expf(accS[nf][0] - mA);
            float e1 = __expf(accS[nf][1] - mA);
            float e2 = __expf(accS[nf][2] - mB);
            float e3 = __expf(accS[nf][3] - mB);
            accS[nf][0] = e0; accS[nf][1] = e1;
            accS[nf][2] = e2; accS[nf][3] = e3;
            sA += e0 + e1; sB += e2 + e3;
        }
        sA += __shfl_xor_sync(0xFFFFFFFF, sA, 1);
        sA += __shfl_xor_sync(0xFFFFFFFF, sA, 2);
        sB += __shfl_xor_sync(0xFFFFFFFF, sB, 1);
        sB += __shfl_xor_sync(0xFFFFFFFF, sB, 2);
        const float invA = 1.0f / fmaxf(sA, 1e-30f);
        const float invB = 1.0f / fmaxf(sB, 1e-30f);
        #pragma unroll
        for (int nf = 0; nf < 8; ++nf) {
            accS[nf][0] *= invA; accS[nf][1] *= invA;
            accS[nf][2] *= invB; accS[nf][3] *= invB;
        }

        // ---- out = P @ V (single fp16 term; V via ldmatrix.trans) ----
        float accO[4][4];
        #pragma unroll
        for (int nf = 0; nf < 4; ++nf)
            #pragma unroll
            for (int r = 0; r < 4; ++r) accO[nf][r] = 0.0f;

        #pragma unroll
        for (int kt = 0; kt < 4; ++kt) {
            uint32_t aph[4];
            #pragma unroll
            for (int q = 0; q < 4; ++q) {
                const int nf = 2 * kt + (q >> 1);
                const int j0 = (q & 1) * 2;
                __half2 hi2 = __floats2half2_rn(accS[nf][j0], accS[nf][j0 + 1]);
                aph[q] = *(uint32_t*)&hi2;
            }
            uint32_t bvh[4][2];
            #pragma unroll
            for (int call = 0; call < 2; ++call) {
                uint32_t off = (uint32_t)(kt * 16 + vrow0) * ROW_B
                             + (call * 16 + vcol0) * 2;
                uint32_t r0, r1, r2, r3;
                LDSM_X4T(r0, r1, r2, r3, vb + off);
                bvh[2 * call][0] = r0; bvh[2 * call][1] = r2;
                bvh[2 * call + 1][0] = r1; bvh[2 * call + 1][1] = r3;
            }
            #pragma unroll
            for (int nf = 0; nf < 4; ++nf)
                MMA_F16(accO[nf], aph, bvh[nf]);
        }

        // ---- epilogue: single fp16 ctx ----
        const size_t wb = (size_t)(b0 + it) * N_TOK;
        #pragma unroll
        for (int half_i = 0; half_i < 2; ++half_i) {
            int row = rA + half_i * 8;
            if (row < N_TOK) {
                size_t obase = (wb + row) * DIM + h * HD;
                #pragma unroll
                for (int nf = 0; nf < 4; ++nf) {
                    int d = nf * 8 + c0;
                    *(__half2*)(ctx + obase + d) = __floats2half2_rn(
                        accO[nf][2 * half_i + 0], accO[nf][2 * half_i + 1]);
                }
            }
        }
    }
}

// ---------------------------------------------------------------------------
extern "C" void kernel_launch(void* const* d_in, const int* in_sizes, int n_in,
                              void* d_out, int out_size)
{
    const float* x      = (const float*)d_in[0];
    const float* qkv_w  = (const float*)d_in[1];
    const float* qkv_b  = (const float*)d_in[2];
    const float* proj_w = (const float*)d_in[3];
    const float* proj_b = (const float*)d_in[4];
    const float* rpb    = (const float*)d_in[5];
    const int*   ridx   = (const int*)d_in[6];
    float* out = (float*)d_out;

    __half *xh, *qkvh, *ctx, *wqh, *wph;
    float *biasf;
    cudaGetSymbolAddress((void**)&xh,    g_xh);
    cudaGetSymbolAddress((void**)&qkvh,  g_qkvh);
    cudaGetSymbolAddress((void**)&ctx,   g_ctx);
    cudaGetSymbolAddress((void**)&wqh,   g_wqh);
    cudaGetSymbolAddress((void**)&wph,   g_wph);
    cudaGetSymbolAddress((void**)&biasf, g_biasf);

    static bool attr_set = false;
    if (!attr_set) {
        cudaFuncSetAttribute(gemm_f16<0>, cudaFuncAttributeMaxDynamicSharedMemorySize, GEMM_SMEM);
        cudaFuncSetAttribute(gemm_f16<1>, cudaFuncAttributeMaxDynamicSharedMemorySize, GEMM_SMEM);
        cudaFuncSetAttribute(attn_kernel, cudaFuncAttributeMaxDynamicSharedMemorySize, ATTN_SMEM);
        attr_set = true;
    }

    // 0) fragment-layout bias table
    bias_frag_kernel<<<HEADS, 128>>>(rpb, ridx, biasf);

    // 1) fp16 conversions
    {
        int n4 = (M_TOT * DIM) / 4;
        split_h1<<<(n4 + 255) / 256, 256>>>(x, xh, n4);
        int w4 = (QKV_N * DIM) / 4;
        split_h1<<<(w4 + 255) / 256, 256>>>(qkv_w, wqh, w4);
        int p4 = (DIM * DIM) / 4;
        split_h1<<<(p4 + 255) / 256, 256>>>(proj_w, wph, p4);
    }

    // 2) QKV GEMM (1-term fp16) -> fp16 qkv (q pre-scaled)
    {
        dim3 grid(QKV_N / 128, M_TOT / 128);   // (9, 1568)
        gemm_f16<1><<<grid, 256, GEMM_SMEM>>>(xh, wqh, qkv_b, nullptr, qkvh, QKV_N);
    }

    // 3) Attention (8 windows x 2 heads per CTA, double-buffered)
    {
        dim3 grid(B_WIN / NW, HEADS / 2);      // (512, 6)
        attn_kernel<<<grid, 256, ATTN_SMEM>>>(qkvh, biasf, ctx);
    }

    // 4) Projection GEMM (1-term fp16) -> fp32 out
    {
        dim3 grid(DIM / 128, M_TOT / 128);     // (3, 1568)
        gemm_f16<0><<<grid, 256, GEMM_SMEM>>>(ctx, wph, proj_b, out, nullptr, DIM);
    }
}